// round 12
// baseline (speedup 1.0000x reference)
#include <cuda_runtime.h>
#include <math.h>
#include <stdint.h>

#define BATCH 16
#define CCH   128
#define NDIM  2000
#define SST   8
#define DCONVK 4
#define DIX   4000
#define DTR   125
#define XCOLS 141     // DTR + 2*SST
#define XSTR  144     // padded xdbl row stride
#define LSEQ  128
#define ROWS  2048
#define DIN2  8000

// ---------------- scratch (static device memory; no allocations) -------------
__device__ float g_m1[ROWS], g_r1[ROWS];
__device__ float g_cm1[CCH], g_cr1[CCH];
__device__ float g_mL[ROWS], g_rL[ROWS];
__device__ float g_m3[ROWS], g_r3[ROWS];
__device__ float g_cm3[CCH], g_cr3[CCH];
__device__ float g_h   [(size_t)ROWS*NDIM];
__device__ float g_h1  [(size_t)ROWS*NDIM];
__device__ float g_outn[(size_t)ROWS*NDIM];
__device__ float g_z   [(size_t)ROWS*DIX];
__device__ float g_xc  [(size_t)ROWS*DIX];
__device__ float g_xdbl[(size_t)ROWS*XSTR];
__device__ float g_dt  [(size_t)ROWS*DIX];
__device__ float g_y   [(size_t)ROWS*DIX];
__device__ float g_res [(size_t)ROWS*NDIM];
// pre-rounded (tf32) weight copies
__device__ float g_win [(size_t)DIN2*NDIM];
__device__ float g_wout[(size_t)NDIM*DIX];
__device__ float g_wx  [(size_t)XCOLS*DIX];
__device__ float g_wdt [(size_t)DIX*128];
__device__ float g_c1w [CCH*CCH];
__device__ float g_c3w [CCH*CCH];

__device__ __forceinline__ uint32_t f2tf(float x) {
    uint32_t r;
    asm("cvt.rna.tf32.f32 %0, %1;" : "=r"(r) : "f"(x));
    return r;
}
__device__ __forceinline__ float rtf(float x) { return __uint_as_float(f2tf(x)); }

// ---------------- reductions -------------------------------------------------
__device__ __forceinline__ void block_reduce2(float& s, float& s2) {
    __shared__ float sh[16];
    #pragma unroll
    for (int o = 16; o; o >>= 1) {
        s  += __shfl_down_sync(0xffffffffu, s,  o);
        s2 += __shfl_down_sync(0xffffffffu, s2, o);
    }
    int w = threadIdx.x >> 5, lane = threadIdx.x & 31;
    if (lane == 0) { sh[w] = s; sh[8 + w] = s2; }
    __syncthreads();
    if (threadIdx.x == 0) {
        float S = 0.f, S2 = 0.f;
        int nw = blockDim.x >> 5;
        for (int i = 0; i < nw; i++) { S += sh[i]; S2 += sh[8 + i]; }
        sh[0] = S; sh[8] = S2;
    }
    __syncthreads();
    s = sh[0]; s2 = sh[8];
}

// per-row mean/rstd over 2000 cols (float4)
__global__ void rowstat_kernel(const float* __restrict__ x, float* __restrict__ mean,
                               float* __restrict__ rstd, float eps) {
    int row = blockIdx.x;
    const float4* p = (const float4*)(x + (size_t)row * NDIM);
    float s = 0.f, s2 = 0.f;
    for (int i = threadIdx.x; i < NDIM / 4; i += blockDim.x) {
        float4 v = p[i];
        s  += v.x + v.y + v.z + v.w;
        s2 += v.x * v.x + v.y * v.y + v.z * v.z + v.w * v.w;
    }
    block_reduce2(s, s2);
    if (threadIdx.x == 0) {
        float m = s / NDIM;
        float var = s2 / NDIM - m * m;
        mean[row] = m;
        rstd[row] = rsqrtf(var + eps);
    }
}

__global__ void chanstat_kernel(const float* __restrict__ x, const float* __restrict__ m,
                                const float* __restrict__ r, float* __restrict__ cmean,
                                float* __restrict__ crstd, float eps) {
    int c = blockIdx.x;
    const float4* x4 = (const float4*)x;
    float s = 0.f, s2 = 0.f;
    for (int idx = threadIdx.x; idx < BATCH * (NDIM / 4); idx += blockDim.x) {
        int b = idx / (NDIM / 4), n4 = idx - b * (NDIM / 4);
        int row = b * CCH + c;
        float mm = m[row], rr = r[row];
        float4 v = x4[(size_t)row * (NDIM / 4) + n4];
        float a0 = (v.x - mm) * rr, a1 = (v.y - mm) * rr;
        float a2 = (v.z - mm) * rr, a3 = (v.w - mm) * rr;
        s  += a0 + a1 + a2 + a3;
        s2 += a0 * a0 + a1 * a1 + a2 * a2 + a3 * a3;
    }
    block_reduce2(s, s2);
    if (threadIdx.x == 0) {
        float mm = s / (BATCH * NDIM);
        float var = s2 / (BATCH * NDIM) - mm * mm;
        cmean[c] = mm;
        crstd[c] = rsqrtf(var + eps);
    }
}

// h = rtf(relu( ((x-m)r - cm)cr*g + b ))  (float4)
__global__ void normrelu_kernel(const float* __restrict__ x, const float* __restrict__ m,
                                const float* __restrict__ r, const float* __restrict__ cm,
                                const float* __restrict__ cr, const float* __restrict__ g,
                                const float* __restrict__ bb, float* __restrict__ out) {
    size_t i = (size_t)blockIdx.x * blockDim.x + threadIdx.x;
    if (i >= (size_t)ROWS * (NDIM / 4)) return;
    int row = (int)(i / (NDIM / 4));
    int c = row & (CCH - 1);
    float a = r[row] * cr[c] * g[c];
    float d = (-m[row]) * a + (-cm[c]) * cr[c] * g[c] + bb[c];
    float4 v = ((const float4*)x)[i];
    float4 o;
    o.x = rtf(fmaxf(v.x * a + d, 0.f));
    o.y = rtf(fmaxf(v.y * a + d, 0.f));
    o.z = rtf(fmaxf(v.z * a + d, 0.f));
    o.w = rtf(fmaxf(v.w * a + d, 0.f));
    ((float4*)out)[i] = o;
}

__global__ void lnapply_kernel(const float* __restrict__ x, const float* __restrict__ m,
                               const float* __restrict__ r, const float* __restrict__ w,
                               const float* __restrict__ bb, float* __restrict__ out) {
    size_t i = (size_t)blockIdx.x * blockDim.x + threadIdx.x;
    if (i >= (size_t)ROWS * (NDIM / 4)) return;
    int row = (int)(i / (NDIM / 4));
    int n4 = (int)(i - (size_t)row * (NDIM / 4));
    float mm = m[row], rr = r[row];
    float4 v = ((const float4*)x)[i];
    float4 wv = ((const float4*)w)[n4];
    float4 bv = ((const float4*)bb)[n4];
    float4 o;
    o.x = rtf((v.x - mm) * rr * wv.x + bv.x);
    o.y = rtf((v.y - mm) * rr * wv.y + bv.y);
    o.z = rtf((v.z - mm) * rr * wv.z + bv.z);
    o.w = rtf((v.w - mm) * rr * wv.w + bv.w);
    ((float4*)out)[i] = o;
}

// selective scan (xdbl stride XSTR; z compact)
__global__ void scan_kernel(const float* __restrict__ dt, const float* __restrict__ xc,
                            const float* __restrict__ xdbl, const float* __restrict__ z,
                            const float* __restrict__ A_log, const float* __restrict__ D_p,
                            float* __restrict__ y) {
    int gidx = blockIdx.x * blockDim.x + threadIdx.x;
    if (gidx >= BATCH * DIX) return;
    int b = gidx / DIX, d = gidx - b * DIX;
    float A[SST], h[SST];
    #pragma unroll
    for (int s = 0; s < SST; s++) {
        A[s] = -expf(A_log[d * SST + s]);
        h[s] = 0.f;
    }
    float Dp = D_p[d];
    for (int l = 0; l < LSEQ; l++) {
        size_t m = (size_t)b * LSEQ + l;
        float dtv = dt[m * DIX + d];
        float u = xc[m * DIX + d];
        float du = dtv * u;
        const float* xr = xdbl + m * XSTR;
        float yv = 0.f;
        #pragma unroll
        for (int s = 0; s < SST; s++) {
            h[s] = __expf(dtv * A[s]) * h[s] + du * xr[DTR + s];
            yv += h[s] * xr[DTR + SST + s];
        }
        float zv = z[m * DIX + d];
        y[m * DIX + d] = rtf((yv + u * Dp) * (zv / (1.f + __expf(-zv))));
    }
}

// pre-round a tensor to tf32 (float4 grid-stride; n % 4 == 0)
__global__ void round_tf32_kernel(const float* __restrict__ src, float* __restrict__ dst,
                                  long n4) {
    long i = (long)blockIdx.x * blockDim.x + threadIdx.x;
    long stride = (long)gridDim.x * blockDim.x;
    for (; i < n4; i += stride) {
        float4 v = ((const float4*)src)[i];
        float4 o;
        o.x = rtf(v.x); o.y = rtf(v.y); o.z = rtf(v.z); o.w = rtf(v.w);
        ((float4*)dst)[i] = o;
    }
}

// round + pad W_dt [DIX,125] -> [DIX,128] (cols >=125 zero)
__global__ void round_pad_wdt(const float* __restrict__ src, float* __restrict__ dst) {
    int i = blockIdx.x * blockDim.x + threadIdx.x;
    if (i >= DIX * 128) return;
    int d = i >> 7, r = i & 127;
    dst[i] = (r < DTR) ? rtf(src[d * DTR + r]) : 0.f;
}

// ---------------- GEMM helpers ------------------------------------------------
#define BSTRN 136

__device__ __forceinline__ void mma_tf32(float* c, const uint32_t* a, const uint32_t* b) {
    asm volatile(
        "mma.sync.aligned.m16n8k8.row.col.f32.tf32.tf32.f32 "
        "{%0,%1,%2,%3}, {%4,%5,%6,%7}, {%8,%9}, {%0,%1,%2,%3};\n"
        : "+f"(c[0]), "+f"(c[1]), "+f"(c[2]), "+f"(c[3])
        : "r"(a[0]), "r"(a[1]), "r"(a[2]), "r"(a[3]), "r"(b[0]), "r"(b[1]));
}

__device__ __forceinline__ void cpa16(uint32_t dst, const void* src, bool pred) {
    int sz = pred ? 16 : 0;
    asm volatile("cp.async.cg.shared.global [%0], [%1], 16, %2;\n"
                 :: "r"(dst), "l"(src), "r"(sz));
}
__device__ __forceinline__ void cp_commit() {
    asm volatile("cp.async.commit_group;\n");
}
template <int n>
__device__ __forceinline__ void cp_wait() {
    asm volatile("cp.async.wait_group %0;\n" :: "n"(n));
}

__device__ __forceinline__ void gemm_epilogue(
    float acc[2][8][4], float* C, int M, int N, int ldc,
    int m0, int n0, int wm, int wn, int lr, int lc,
    const float* biasM, const float* biasN, const float* resid, int act) {
    #pragma unroll
    for (int im = 0; im < 2; im++) {
        #pragma unroll
        for (int rr = 0; rr < 2; rr++) {
            int gm = m0 + wm + im * 16 + lr + rr * 8;
            if (gm >= M) continue;
            float bm = biasM ? biasM[gm] : 0.f;
            #pragma unroll
            for (int in_ = 0; in_ < 8; in_++) {
                int gn = n0 + wn + in_ * 8 + 2 * lc;
                float v0 = acc[im][in_][rr * 2 + 0] + bm;
                float v1 = acc[im][in_][rr * 2 + 1] + bm;
                if (biasN) {
                    if (gn + 0 < N) v0 += biasN[gn + 0];
                    if (gn + 1 < N) v1 += biasN[gn + 1];
                }
                if (resid) {
                    if (gn + 0 < N) v0 += resid[(long)gm * ldc + gn + 0];
                    if (gn + 1 < N) v1 += resid[(long)gm * ldc + gn + 1];
                }
                if (act == 2) {
                    v0 = fmaxf(v0, 0.f) + __logf(1.f + __expf(-fabsf(v0)));
                    v1 = fmaxf(v1, 0.f) + __logf(1.f + __expf(-fabsf(v1)));
                }
                float* cp = &C[(long)gm * ldc + gn];
                if (gn + 1 < N && ((((uintptr_t)cp) & 7) == 0)) {
                    *(float2*)cp = make_float2(v0, v1);
                } else {
                    if (gn + 0 < N) cp[0] = v0;
                    if (gn + 1 < N) cp[1] = v1;
                }
            }
        }
    }
}

// ---------------- pipelined TF32 GEMM -----------------------------------------
// 4-stage cp.async, 128x128 tile, BK=16, 8 warps.
// FUSE=1 (W_in): epilogue stages tile in smem, applies causal depthwise conv
// + SiLU for cols < nsplit (writes xcout), plain copy for cols >= nsplit (zout).
#define STAGES 4
#define ASZ    3072
#define BSZ    3072
#define STG_W  (ASZ + BSZ)
#define PIPE_SMEM (STAGES * STG_W * 4)
#define TSTR   132   // fused-epilogue tile stride

template <int TRANSB, int FUSE>
__global__ void __launch_bounds__(256, 2) gemm_tf32_pipe(
    const float* __restrict__ A, const float* __restrict__ Bp, float* __restrict__ C,
    int M, int N, int K, int lda, int ldb, int ldc,
    long sA, long sB, long sC,
    const float* __restrict__ biasM, const float* __restrict__ biasN,
    const float* __restrict__ resid, long sR, int act,
    const float* __restrict__ cw, const float* __restrict__ cb,
    float* __restrict__ xcout, float* __restrict__ zout, int nsplit) {
    constexpr int ASTR = TRANSB ? 24 : 20;
    extern __shared__ float sm[];
    uint32_t smbase = (uint32_t)__cvta_generic_to_shared(sm);

    int z = blockIdx.z;
    A  += (long)z * sA;
    Bp += (long)z * sB;
    C  += (long)z * sC;

    int m0 = blockIdx.y * 128, n0 = blockIdx.x * 128;
    int tid = threadIdx.x;
    int warp = tid >> 5, lane = tid & 31;
    int wm = (warp >> 1) * 32;
    int wn = (warp & 1) * 64;
    int lr = lane >> 2, lc = lane & 3;

    float acc[2][8][4];
    #pragma unroll
    for (int i = 0; i < 2; i++)
        #pragma unroll
        for (int j = 0; j < 8; j++)
            #pragma unroll
            for (int q = 0; q < 4; q++) acc[i][j][q] = 0.f;

    int a_row[2], a_c4[2];
    #pragma unroll
    for (int j = 0; j < 2; j++) {
        int f = tid + j * 256;
        a_row[j] = f >> 2;
        a_c4[j]  = (f & 3) * 4;
    }

    auto load_stage = [&](int k0, int st) {
        uint32_t abase = smbase + (uint32_t)(st * STG_W * 4);
        uint32_t bbase = abase + (uint32_t)(ASZ * 4);
        #pragma unroll
        for (int j = 0; j < 2; j++) {
            int row = a_row[j], c4 = a_c4[j];
            int gm = m0 + row;
            cpa16(abase + (uint32_t)((row * ASTR + c4) * 4),
                  A + (long)gm * lda + k0 + c4, gm < M);
        }
        if (TRANSB) {
            #pragma unroll
            for (int j = 0; j < 2; j++) {
                int nn = a_row[j], k4 = a_c4[j];
                int gn = n0 + nn;
                cpa16(bbase + (uint32_t)((nn * ASTR + k4) * 4),
                      Bp + (long)gn * ldb + k0 + k4, gn < N);
            }
        } else {
            #pragma unroll
            for (int j = 0; j < 2; j++) {
                int f = tid + j * 256;
                int kk = f >> 5, n4 = (f & 31) * 4;
                int gn = n0 + n4;
                cpa16(bbase + (uint32_t)((kk * BSTRN + n4) * 4),
                      Bp + (long)(k0 + kk) * ldb + gn, gn < N);
            }
        }
    };

    int niter = K >> 4;

    #pragma unroll
    for (int s = 0; s < STAGES - 1; s++) {
        load_stage(s * 16, s);
        cp_commit();
    }

    for (int it = 0; it < niter; it++) {
        int kp = it + STAGES - 1;
        if (kp < niter) load_stage(kp * 16, kp % STAGES);
        cp_commit();
        cp_wait<STAGES - 1>();
        __syncthreads();

        int st = it % STAGES;
        const float* Asm = sm + st * STG_W;
        const float* Bsm = Asm + ASZ;

        #pragma unroll
        for (int kk = 0; kk < 2; kk++) {
            int kb = kk * 8;
            uint32_t af[2][4];
            uint32_t bfr[8][2];
            if (TRANSB) {
                #pragma unroll
                for (int im = 0; im < 2; im++) {
                    int r = wm + im * 16 + lr;
                    uint2 v0 = *(const uint2*)&Asm[r * ASTR + kb + 2 * lc];
                    uint2 v1 = *(const uint2*)&Asm[(r + 8) * ASTR + kb + 2 * lc];
                    af[im][0] = v0.x; af[im][1] = v1.x;
                    af[im][2] = v0.y; af[im][3] = v1.y;
                }
                #pragma unroll
                for (int in_ = 0; in_ < 8; in_++) {
                    int nn = wn + in_ * 8 + lr;
                    uint2 w = *(const uint2*)&Bsm[nn * ASTR + kb + 2 * lc];
                    bfr[in_][0] = w.x; bfr[in_][1] = w.y;
                }
            } else {
                const uint32_t* Au = (const uint32_t*)Asm;
                const uint32_t* Bu = (const uint32_t*)Bsm;
                #pragma unroll
                for (int im = 0; im < 2; im++) {
                    int r = wm + im * 16 + lr;
                    af[im][0] = Au[r * ASTR + kb + lc];
                    af[im][1] = Au[(r + 8) * ASTR + kb + lc];
                    af[im][2] = Au[r * ASTR + kb + lc + 4];
                    af[im][3] = Au[(r + 8) * ASTR + kb + lc + 4];
                }
                #pragma unroll
                for (int in_ = 0; in_ < 8; in_++) {
                    int nn = wn + in_ * 8 + lr;
                    bfr[in_][0] = Bu[(kb + lc) * BSTRN + nn];
                    bfr[in_][1] = Bu[(kb + lc + 4) * BSTRN + nn];
                }
            }
            #pragma unroll
            for (int im = 0; im < 2; im++)
                #pragma unroll
                for (int in_ = 0; in_ < 8; in_++)
                    mma_tf32(acc[im][in_], af[im], bfr[in_]);
        }
        __syncthreads();
    }

    if (FUSE) {
        // stage tile into smem: rows 0..127 of this batch's sequence, cols n0..n0+127
        float* st = sm;   // 128 x TSTR floats (67.6 KB < PIPE_SMEM)
        #pragma unroll
        for (int im = 0; im < 2; im++)
            #pragma unroll
            for (int rr = 0; rr < 2; rr++) {
                int row = wm + im * 16 + lr + rr * 8;
                #pragma unroll
                for (int in_ = 0; in_ < 8; in_++) {
                    int col = wn + in_ * 8 + 2 * lc;
                    *(float2*)&st[row * TSTR + col] =
                        make_float2(acc[im][in_][rr * 2], acc[im][in_][rr * 2 + 1]);
                }
            }
        __syncthreads();

        int c = tid & 127;
        int rbase = (tid >> 7) * 64;
        int gn = n0 + c;
        if (gn < nsplit) {
            int d = gn;
            float w0 = cw[d * 4 + 0], w1 = cw[d * 4 + 1];
            float w2 = cw[d * 4 + 2], w3 = cw[d * 4 + 3];
            float bias = cb[d];
            float xm3 = (rbase >= 3) ? st[(rbase - 3) * TSTR + c] : 0.f;
            float xm2 = (rbase >= 2) ? st[(rbase - 2) * TSTR + c] : 0.f;
            float xm1 = (rbase >= 1) ? st[(rbase - 1) * TSTR + c] : 0.f;
            for (int r = 0; r < 64; r++) {
                float x0 = st[(rbase + r) * TSTR + c];
                float a = bias + xm3 * w0 + xm2 * w1 + xm1 * w2 + x0 * w3;
                xcout[(size_t)(m0 + rbase + r) * DIX + d] =
                    rtf(a * (1.f / (1.f + __expf(-a))));
                xm3 = xm2; xm2 = xm1; xm1 = x0;
            }
        } else if (gn < N) {
            int d = gn - nsplit;
            for (int r = 0; r < 64; r++)
                zout[(size_t)(m0 + rbase + r) * DIX + d] = st[(rbase + r) * TSTR + c];
        }
        return;
    }

    if (resid) resid += (long)z * sR;
    gemm_epilogue(acc, C, M, N, ldc, m0, n0, wm, wn, lr, lc, biasM, biasN, resid, act);
}

// ---------------- host side --------------------------------------------------
static void launch_gemm(const float* A, const float* B, float* C,
                        int M, int N, int K, int lda, int ldb, int ldc,
                        long sA, long sB, long sC, int batch, int transB,
                        const float* biasM, const float* biasN,
                        const float* resid, long sR, int act) {
    dim3 grid((N + 127) / 128, (M + 127) / 128, batch);
    if (transB) {
        cudaFuncSetAttribute(gemm_tf32_pipe<1, 0>,
                             cudaFuncAttributeMaxDynamicSharedMemorySize, PIPE_SMEM);
        gemm_tf32_pipe<1, 0><<<grid, 256, PIPE_SMEM>>>(
            A, B, C, M, N, K, lda, ldb, ldc, sA, sB, sC, biasM, biasN,
            resid, sR, act, nullptr, nullptr, nullptr, nullptr, 0);
    } else {
        cudaFuncSetAttribute(gemm_tf32_pipe<0, 0>,
                             cudaFuncAttributeMaxDynamicSharedMemorySize, PIPE_SMEM);
        gemm_tf32_pipe<0, 0><<<grid, 256, PIPE_SMEM>>>(
            A, B, C, M, N, K, lda, ldb, ldc, sA, sB, sC, biasM, biasN,
            resid, sR, act, nullptr, nullptr, nullptr, nullptr, 0);
    }
}

static void launch_gemm_fused_conv(const float* A, const float* B,
                                   int M, int N, int K, int lda, int ldb,
                                   const float* cw, const float* cb,
                                   float* xcout, float* zout) {
    dim3 grid((N + 127) / 128, (M + 127) / 128, 1);
    cudaFuncSetAttribute(gemm_tf32_pipe<1, 1>,
                         cudaFuncAttributeMaxDynamicSharedMemorySize, PIPE_SMEM);
    gemm_tf32_pipe<1, 1><<<grid, 256, PIPE_SMEM>>>(
        A, B, nullptr, M, N, K, lda, ldb, 0, 0, 0, 0, nullptr, nullptr,
        nullptr, 0, 0, cw, cb, xcout, zout, DIX);
}

extern "C" void kernel_launch(void* const* d_in, const int* in_sizes, int n_in,
                              void* d_out, int out_size) {
    const float* x       = (const float*)d_in[0];
    const float* bn1_g   = (const float*)d_in[1];
    const float* bn1_b   = (const float*)d_in[2];
    const float* conv1_w = (const float*)d_in[3];
    const float* conv1_b = (const float*)d_in[4];
    const float* ln_w    = (const float*)d_in[5];
    const float* ln_b    = (const float*)d_in[6];
    const float* W_in    = (const float*)d_in[7];
    const float* convm_w = (const float*)d_in[8];
    const float* convm_b = (const float*)d_in[9];
    const float* W_x     = (const float*)d_in[10];
    const float* W_dt    = (const float*)d_in[11];
    const float* b_dt    = (const float*)d_in[12];
    const float* A_log   = (const float*)d_in[13];
    const float* D_p     = (const float*)d_in[14];
    const float* W_out   = (const float*)d_in[15];
    const float* bn3_g   = (const float*)d_in[16];
    const float* bn3_b   = (const float*)d_in[17];
    const float* conv3_w = (const float*)d_in[18];
    const float* conv3_b = (const float*)d_in[19];
    float* out = (float*)d_out;

    float *pm1, *pr1, *pcm1, *pcr1, *pmL, *prL, *pm3, *pr3, *pcm3, *pcr3;
    float *ph, *ph1, *poutn, *pz, *pxc, *pxdbl, *pdt, *py, *pres;
    float *pwin, *pwout, *pwx, *pwdt, *pc1w, *pc3w;
    cudaGetSymbolAddress((void**)&pm1,  g_m1);
    cudaGetSymbolAddress((void**)&pr1,  g_r1);
    cudaGetSymbolAddress((void**)&pcm1, g_cm1);
    cudaGetSymbolAddress((void**)&pcr1, g_cr1);
    cudaGetSymbolAddress((void**)&pmL,  g_mL);
    cudaGetSymbolAddress((void**)&prL,  g_rL);
    cudaGetSymbolAddress((void**)&pm3,  g_m3);
    cudaGetSymbolAddress((void**)&pr3,  g_r3);
    cudaGetSymbolAddress((void**)&pcm3, g_cm3);
    cudaGetSymbolAddress((void**)&pcr3, g_cr3);
    cudaGetSymbolAddress((void**)&ph,    g_h);
    cudaGetSymbolAddress((void**)&ph1,   g_h1);
    cudaGetSymbolAddress((void**)&poutn, g_outn);
    cudaGetSymbolAddress((void**)&pz,    g_z);
    cudaGetSymbolAddress((void**)&pxc,   g_xc);
    cudaGetSymbolAddress((void**)&pxdbl, g_xdbl);
    cudaGetSymbolAddress((void**)&pdt,   g_dt);
    cudaGetSymbolAddress((void**)&py,    g_y);
    cudaGetSymbolAddress((void**)&pres,  g_res);
    cudaGetSymbolAddress((void**)&pwin,  g_win);
    cudaGetSymbolAddress((void**)&pwout, g_wout);
    cudaGetSymbolAddress((void**)&pwx,   g_wx);
    cudaGetSymbolAddress((void**)&pwdt,  g_wdt);
    cudaGetSymbolAddress((void**)&pc1w,  g_c1w);
    cudaGetSymbolAddress((void**)&pc3w,  g_c3w);

    const int EW_BLK = 256;
    const size_t nBCN4 = (size_t)ROWS * (NDIM / 4);
    int gBCN4 = (int)((nBCN4 + EW_BLK - 1) / EW_BLK);

    // ---- pre-round weights to tf32 ----
    round_tf32_kernel<<<1024, 256>>>(W_in,  pwin,  (long)DIN2 * NDIM / 4);
    round_tf32_kernel<<<1024, 256>>>(W_out, pwout, (long)NDIM * DIX / 4);
    round_tf32_kernel<<<256,  256>>>(W_x,   pwx,   (long)XCOLS * DIX / 4);
    round_tf32_kernel<<<16,   256>>>(conv1_w, pc1w, (long)CCH * CCH / 4);
    round_tf32_kernel<<<16,   256>>>(conv3_w, pc3w, (long)CCH * CCH / 4);
    round_pad_wdt<<<(DIX * 128 + 255) / 256, 256>>>(W_dt, pwdt);

    // ---- Block 1: inorm -> bnorm -> relu -> 1x1 conv ----
    rowstat_kernel<<<ROWS, 256>>>(x, pm1, pr1, 1e-3f);
    chanstat_kernel<<<CCH, 256>>>(x, pm1, pr1, pcm1, pcr1, 1e-5f);
    normrelu_kernel<<<gBCN4, EW_BLK>>>(x, pm1, pr1, pcm1, pcr1, bn1_g, bn1_b, ph);
    launch_gemm(pc1w, ph, ph1, CCH, NDIM, CCH, CCH, NDIM, NDIM,
                0, (long)CCH * NDIM, (long)CCH * NDIM, BATCH, 0,
                conv1_b, nullptr, nullptr, 0, 0);

    // ---- LayerNorm over N ----
    rowstat_kernel<<<ROWS, 256>>>(ph1, pmL, prL, 1e-5f);
    lnapply_kernel<<<gBCN4, EW_BLK>>>(ph1, pmL, prL, ln_w, ln_b, poutn);

    // ---- Mamba ----
    // xz GEMM fused with depthwise conv + silu: writes xc and z directly
    launch_gemm_fused_conv(poutn, pwin, ROWS, DIN2, NDIM, NDIM, NDIM,
                           convm_w, convm_b, pxc, pz);
    // xdbl = xc @ W_x^T  (padded stride XSTR)
    launch_gemm(pxc, pwx, pxdbl, ROWS, XCOLS, DIX, DIX, DIX, XSTR,
                0, 0, 0, 1, 1, nullptr, nullptr, nullptr, 0, 0);
    // dt = softplus(xdbl[:, :128] @ wdt_pad^T + b_dt)   (pad cols hit zero weights)
    launch_gemm(pxdbl, pwdt, pdt, ROWS, DIX, 128, XSTR, 128, DIX,
                0, 0, 0, 1, 1, nullptr, b_dt, nullptr, 0, 2);
    scan_kernel<<<(BATCH * DIX + 255) / 256, 256>>>(pdt, pxc, pxdbl, pz,
                                                    A_log, D_p, py);
    launch_gemm(py, pwout, pres, ROWS, NDIM, DIX, DIX, DIX, NDIM,
                0, 0, 0, 1, 1, nullptr, nullptr, ph1, 0, 0);

    // ---- Block 3 ----
    rowstat_kernel<<<ROWS, 256>>>(pres, pm3, pr3, 1e-3f);
    chanstat_kernel<<<CCH, 256>>>(pres, pm3, pr3, pcm3, pcr3, 1e-5f);
    normrelu_kernel<<<gBCN4, EW_BLK>>>(pres, pm3, pr3, pcm3, pcr3, bn3_g, bn3_b, ph);
    launch_gemm(pc3w, ph, out, CCH, NDIM, CCH, CCH, NDIM, NDIM,
                0, (long)CCH * NDIM, (long)CCH * NDIM, BATCH, 0,
                conv3_b, nullptr, x, (long)CCH * NDIM, 0);
}

// round 13
// speedup vs baseline: 1.4666x; 1.4666x over previous
#include <cuda_runtime.h>
#include <math.h>
#include <stdint.h>

#define BATCH 16
#define CCH   128
#define NDIM  2000
#define SST   8
#define DCONVK 4
#define DIX   4000
#define DTR   125
#define XCOLS 141     // DTR + 2*SST
#define XSTR  144     // padded xdbl row stride
#define LSEQ  128
#define ROWS  2048
#define DIN2  8000

// ---------------- scratch (static device memory; no allocations) -------------
__device__ float g_m1[ROWS], g_r1[ROWS];
__device__ float g_cm1[CCH], g_cr1[CCH];
__device__ float g_mL[ROWS], g_rL[ROWS];
__device__ float g_m3[ROWS], g_r3[ROWS];
__device__ float g_cm3[CCH], g_cr3[CCH];
__device__ float g_h   [(size_t)ROWS*NDIM];
__device__ float g_h1  [(size_t)ROWS*NDIM];
__device__ float g_outn[(size_t)ROWS*NDIM];
__device__ float g_xz  [(size_t)ROWS*DIN2];
__device__ float g_xc  [(size_t)ROWS*DIX];
__device__ float g_xdbl[(size_t)ROWS*XSTR];
__device__ float g_dt  [(size_t)ROWS*DIX];
__device__ float g_y   [(size_t)ROWS*DIX];
__device__ float g_res [(size_t)ROWS*NDIM];
// pre-rounded (tf32) weight copies
__device__ float g_win [(size_t)DIN2*NDIM];
__device__ float g_wout[(size_t)NDIM*DIX];
__device__ float g_wx  [(size_t)XCOLS*DIX];
__device__ float g_wdt [(size_t)DIX*128];
__device__ float g_c1w [CCH*CCH];
__device__ float g_c3w [CCH*CCH];

__device__ __forceinline__ uint32_t f2tf(float x) {
    uint32_t r;
    asm("cvt.rna.tf32.f32 %0, %1;" : "=r"(r) : "f"(x));
    return r;
}
__device__ __forceinline__ float rtf(float x) { return __uint_as_float(f2tf(x)); }

// ---------------- reductions -------------------------------------------------
__device__ __forceinline__ void block_reduce2(float& s, float& s2) {
    __shared__ float sh[16];
    #pragma unroll
    for (int o = 16; o; o >>= 1) {
        s  += __shfl_down_sync(0xffffffffu, s,  o);
        s2 += __shfl_down_sync(0xffffffffu, s2, o);
    }
    int w = threadIdx.x >> 5, lane = threadIdx.x & 31;
    if (lane == 0) { sh[w] = s; sh[8 + w] = s2; }
    __syncthreads();
    if (threadIdx.x == 0) {
        float S = 0.f, S2 = 0.f;
        int nw = blockDim.x >> 5;
        for (int i = 0; i < nw; i++) { S += sh[i]; S2 += sh[8 + i]; }
        sh[0] = S; sh[8] = S2;
    }
    __syncthreads();
    s = sh[0]; s2 = sh[8];
}

__global__ void rowstat_kernel(const float* __restrict__ x, float* __restrict__ mean,
                               float* __restrict__ rstd, float eps) {
    int row = blockIdx.x;
    const float4* p = (const float4*)(x + (size_t)row * NDIM);
    float s = 0.f, s2 = 0.f;
    for (int i = threadIdx.x; i < NDIM / 4; i += blockDim.x) {
        float4 v = p[i];
        s  += v.x + v.y + v.z + v.w;
        s2 += v.x * v.x + v.y * v.y + v.z * v.z + v.w * v.w;
    }
    block_reduce2(s, s2);
    if (threadIdx.x == 0) {
        float m = s / NDIM;
        float var = s2 / NDIM - m * m;
        mean[row] = m;
        rstd[row] = rsqrtf(var + eps);
    }
}

__global__ void chanstat_kernel(const float* __restrict__ x, const float* __restrict__ m,
                                const float* __restrict__ r, float* __restrict__ cmean,
                                float* __restrict__ crstd, float eps) {
    int c = blockIdx.x;
    const float4* x4 = (const float4*)x;
    float s = 0.f, s2 = 0.f;
    for (int idx = threadIdx.x; idx < BATCH * (NDIM / 4); idx += blockDim.x) {
        int b = idx / (NDIM / 4), n4 = idx - b * (NDIM / 4);
        int row = b * CCH + c;
        float mm = m[row], rr = r[row];
        float4 v = x4[(size_t)row * (NDIM / 4) + n4];
        float a0 = (v.x - mm) * rr, a1 = (v.y - mm) * rr;
        float a2 = (v.z - mm) * rr, a3 = (v.w - mm) * rr;
        s  += a0 + a1 + a2 + a3;
        s2 += a0 * a0 + a1 * a1 + a2 * a2 + a3 * a3;
    }
    block_reduce2(s, s2);
    if (threadIdx.x == 0) {
        float mm = s / (BATCH * NDIM);
        float var = s2 / (BATCH * NDIM) - mm * mm;
        cmean[c] = mm;
        crstd[c] = rsqrtf(var + eps);
    }
}

__global__ void normrelu_kernel(const float* __restrict__ x, const float* __restrict__ m,
                                const float* __restrict__ r, const float* __restrict__ cm,
                                const float* __restrict__ cr, const float* __restrict__ g,
                                const float* __restrict__ bb, float* __restrict__ out) {
    size_t i = (size_t)blockIdx.x * blockDim.x + threadIdx.x;
    if (i >= (size_t)ROWS * (NDIM / 4)) return;
    int row = (int)(i / (NDIM / 4));
    int c = row & (CCH - 1);
    float a = r[row] * cr[c] * g[c];
    float d = (-m[row]) * a + (-cm[c]) * cr[c] * g[c] + bb[c];
    float4 v = ((const float4*)x)[i];
    float4 o;
    o.x = rtf(fmaxf(v.x * a + d, 0.f));
    o.y = rtf(fmaxf(v.y * a + d, 0.f));
    o.z = rtf(fmaxf(v.z * a + d, 0.f));
    o.w = rtf(fmaxf(v.w * a + d, 0.f));
    ((float4*)out)[i] = o;
}

__global__ void lnapply_kernel(const float* __restrict__ x, const float* __restrict__ m,
                               const float* __restrict__ r, const float* __restrict__ w,
                               const float* __restrict__ bb, float* __restrict__ out) {
    size_t i = (size_t)blockIdx.x * blockDim.x + threadIdx.x;
    if (i >= (size_t)ROWS * (NDIM / 4)) return;
    int row = (int)(i / (NDIM / 4));
    int n4 = (int)(i - (size_t)row * (NDIM / 4));
    float mm = m[row], rr = r[row];
    float4 v = ((const float4*)x)[i];
    float4 wv = ((const float4*)w)[n4];
    float4 bv = ((const float4*)bb)[n4];
    float4 o;
    o.x = rtf((v.x - mm) * rr * wv.x + bv.x);
    o.y = rtf((v.y - mm) * rr * wv.y + bv.y);
    o.z = rtf((v.z - mm) * rr * wv.z + bv.z);
    o.w = rtf((v.w - mm) * rr * wv.w + bv.w);
    ((float4*)out)[i] = o;
}

// depthwise causal conv + silu, float4 over d
__global__ void convm_silu_kernel(const float* __restrict__ xz, const float* __restrict__ cw,
                                  const float* __restrict__ cb, float* __restrict__ xc) {
    size_t i = (size_t)blockIdx.x * blockDim.x + threadIdx.x;     // (mrow, d4)
    if (i >= (size_t)ROWS * (DIX / 4)) return;
    int d4 = (int)(i % (DIX / 4));
    size_t mrow = i / (DIX / 4);
    int l = (int)(mrow & (LSEQ - 1));
    size_t b = mrow >> 7;
    int d = d4 * 4;
    float4 acc = ((const float4*)cb)[d4];
    // cw rows d..d+3 (4 taps each) = 4 float4 loads
    float4 w0 = ((const float4*)cw)[d + 0];
    float4 w1 = ((const float4*)cw)[d + 1];
    float4 w2 = ((const float4*)cw)[d + 2];
    float4 w3 = ((const float4*)cw)[d + 3];
    #pragma unroll
    for (int k = 0; k < DCONVK; k++) {
        int ls = l + k - (DCONVK - 1);
        if (ls >= 0) {
            float4 v = *(const float4*)(xz + (b * LSEQ + ls) * (size_t)DIN2 + d);
            float tk0 = (&w0.x)[k], tk1 = (&w1.x)[k], tk2 = (&w2.x)[k], tk3 = (&w3.x)[k];
            acc.x += v.x * tk0; acc.y += v.y * tk1;
            acc.z += v.z * tk2; acc.w += v.w * tk3;
        }
    }
    float4 o;
    o.x = rtf(acc.x * (1.f / (1.f + __expf(-acc.x))));
    o.y = rtf(acc.y * (1.f / (1.f + __expf(-acc.y))));
    o.z = rtf(acc.z * (1.f / (1.f + __expf(-acc.z))));
    o.w = rtf(acc.w * (1.f / (1.f + __expf(-acc.w))));
    ((float4*)xc)[i] = o;
}

// selective scan (xdbl stride XSTR; z = second half of xz rows)
__global__ void scan_kernel(const float* __restrict__ dt, const float* __restrict__ xc,
                            const float* __restrict__ xdbl, const float* __restrict__ xz,
                            const float* __restrict__ A_log, const float* __restrict__ D_p,
                            float* __restrict__ y) {
    int gidx = blockIdx.x * blockDim.x + threadIdx.x;
    if (gidx >= BATCH * DIX) return;
    int b = gidx / DIX, d = gidx - b * DIX;
    float A[SST], h[SST];
    #pragma unroll
    for (int s = 0; s < SST; s++) {
        A[s] = -expf(A_log[d * SST + s]);
        h[s] = 0.f;
    }
    float Dp = D_p[d];
    for (int l = 0; l < LSEQ; l++) {
        size_t m = (size_t)b * LSEQ + l;
        float dtv = dt[m * DIX + d];
        float u = xc[m * DIX + d];
        float du = dtv * u;
        const float* xr = xdbl + m * XSTR;
        float yv = 0.f;
        #pragma unroll
        for (int s = 0; s < SST; s++) {
            h[s] = __expf(dtv * A[s]) * h[s] + du * xr[DTR + s];
            yv += h[s] * xr[DTR + SST + s];
        }
        float zv = xz[m * DIN2 + DIX + d];
        y[m * DIX + d] = rtf((yv + u * Dp) * (zv / (1.f + __expf(-zv))));
    }
}

// pre-round a tensor to tf32 (float4 grid-stride)
__global__ void round_tf32_kernel(const float* __restrict__ src, float* __restrict__ dst,
                                  long n4) {
    long i = (long)blockIdx.x * blockDim.x + threadIdx.x;
    long stride = (long)gridDim.x * blockDim.x;
    for (; i < n4; i += stride) {
        float4 v = ((const float4*)src)[i];
        float4 o;
        o.x = rtf(v.x); o.y = rtf(v.y); o.z = rtf(v.z); o.w = rtf(v.w);
        ((float4*)dst)[i] = o;
    }
}

// round + pad W_dt [DIX,125] -> [DIX,128]
__global__ void round_pad_wdt(const float* __restrict__ src, float* __restrict__ dst) {
    int i = blockIdx.x * blockDim.x + threadIdx.x;
    if (i >= DIX * 128) return;
    int d = i >> 7, r = i & 127;
    dst[i] = (r < DTR) ? rtf(src[d * DTR + r]) : 0.f;
}

// ---------------- GEMM helpers ------------------------------------------------
#define BSTRN 136

__device__ __forceinline__ void mma_tf32(float* c, const uint32_t* a, const uint32_t* b) {
    asm volatile(
        "mma.sync.aligned.m16n8k8.row.col.f32.tf32.tf32.f32 "
        "{%0,%1,%2,%3}, {%4,%5,%6,%7}, {%8,%9}, {%0,%1,%2,%3};\n"
        : "+f"(c[0]), "+f"(c[1]), "+f"(c[2]), "+f"(c[3])
        : "r"(a[0]), "r"(a[1]), "r"(a[2]), "r"(a[3]), "r"(b[0]), "r"(b[1]));
}

__device__ __forceinline__ void cpa16(uint32_t dst, const void* src, bool pred) {
    int sz = pred ? 16 : 0;
    asm volatile("cp.async.cg.shared.global [%0], [%1], 16, %2;\n"
                 :: "r"(dst), "l"(src), "r"(sz));
}
__device__ __forceinline__ void cp_commit() {
    asm volatile("cp.async.commit_group;\n");
}
template <int n>
__device__ __forceinline__ void cp_wait() {
    asm volatile("cp.async.wait_group %0;\n" :: "n"(n));
}

__device__ __forceinline__ void gemm_epilogue(
    float acc[2][8][4], float* C, int M, int N, int ldc,
    int m0, int n0, int wm, int wn, int lr, int lc,
    const float* biasM, const float* biasN, const float* resid, int act) {
    #pragma unroll
    for (int im = 0; im < 2; im++) {
        #pragma unroll
        for (int rr = 0; rr < 2; rr++) {
            int gm = m0 + wm + im * 16 + lr + rr * 8;
            if (gm >= M) continue;
            float bm = biasM ? biasM[gm] : 0.f;
            #pragma unroll
            for (int in_ = 0; in_ < 8; in_++) {
                int gn = n0 + wn + in_ * 8 + 2 * lc;
                float v0 = acc[im][in_][rr * 2 + 0] + bm;
                float v1 = acc[im][in_][rr * 2 + 1] + bm;
                if (biasN) {
                    if (gn + 0 < N) v0 += biasN[gn + 0];
                    if (gn + 1 < N) v1 += biasN[gn + 1];
                }
                if (resid) {
                    if (gn + 0 < N) v0 += resid[(long)gm * ldc + gn + 0];
                    if (gn + 1 < N) v1 += resid[(long)gm * ldc + gn + 1];
                }
                if (act == 2) {
                    v0 = fmaxf(v0, 0.f) + __logf(1.f + __expf(-fabsf(v0)));
                    v1 = fmaxf(v1, 0.f) + __logf(1.f + __expf(-fabsf(v1)));
                }
                float* cp = &C[(long)gm * ldc + gn];
                if (gn + 1 < N && ((((uintptr_t)cp) & 7) == 0)) {
                    *(float2*)cp = make_float2(v0, v1);
                } else {
                    if (gn + 0 < N) cp[0] = v0;
                    if (gn + 1 < N) cp[1] = v1;
                }
            }
        }
    }
}

// ---------------- pipelined TF32 GEMM (all GEMMs; clean mainloop) -------------
#define STAGES 4
#define ASZ    3072
#define BSZ    3072
#define STG_W  (ASZ + BSZ)
#define PIPE_SMEM (STAGES * STG_W * 4)

template <int TRANSB>
__global__ void __launch_bounds__(256, 2) gemm_tf32_pipe(
    const float* __restrict__ A, const float* __restrict__ Bp, float* __restrict__ C,
    int M, int N, int K, int lda, int ldb, int ldc,
    long sA, long sB, long sC,
    const float* __restrict__ biasM, const float* __restrict__ biasN,
    const float* __restrict__ resid, long sR, int act) {
    constexpr int ASTR = TRANSB ? 24 : 20;
    extern __shared__ float sm[];
    uint32_t smbase = (uint32_t)__cvta_generic_to_shared(sm);

    int z = blockIdx.z;
    A  += (long)z * sA;
    Bp += (long)z * sB;
    C  += (long)z * sC;

    int m0 = blockIdx.y * 128, n0 = blockIdx.x * 128;
    int tid = threadIdx.x;
    int warp = tid >> 5, lane = tid & 31;
    int wm = (warp >> 1) * 32;
    int wn = (warp & 1) * 64;
    int lr = lane >> 2, lc = lane & 3;

    float acc[2][8][4];
    #pragma unroll
    for (int i = 0; i < 2; i++)
        #pragma unroll
        for (int j = 0; j < 8; j++)
            #pragma unroll
            for (int q = 0; q < 4; q++) acc[i][j][q] = 0.f;

    int a_row[2], a_c4[2];
    #pragma unroll
    for (int j = 0; j < 2; j++) {
        int f = tid + j * 256;
        a_row[j] = f >> 2;
        a_c4[j]  = (f & 3) * 4;
    }

    auto load_stage = [&](int k0, int st) {
        uint32_t abase = smbase + (uint32_t)(st * STG_W * 4);
        uint32_t bbase = abase + (uint32_t)(ASZ * 4);
        #pragma unroll
        for (int j = 0; j < 2; j++) {
            int row = a_row[j], c4 = a_c4[j];
            int gm = m0 + row;
            cpa16(abase + (uint32_t)((row * ASTR + c4) * 4),
                  A + (long)gm * lda + k0 + c4, gm < M);
        }
        if (TRANSB) {
            #pragma unroll
            for (int j = 0; j < 2; j++) {
                int nn = a_row[j], k4 = a_c4[j];
                int gn = n0 + nn;
                cpa16(bbase + (uint32_t)((nn * ASTR + k4) * 4),
                      Bp + (long)gn * ldb + k0 + k4, gn < N);
            }
        } else {
            #pragma unroll
            for (int j = 0; j < 2; j++) {
                int f = tid + j * 256;
                int kk = f >> 5, n4 = (f & 31) * 4;
                int gn = n0 + n4;
                cpa16(bbase + (uint32_t)((kk * BSTRN + n4) * 4),
                      Bp + (long)(k0 + kk) * ldb + gn, gn < N);
            }
        }
    };

    int niter = K >> 4;

    #pragma unroll
    for (int s = 0; s < STAGES - 1; s++) {
        load_stage(s * 16, s);
        cp_commit();
    }

    for (int it = 0; it < niter; it++) {
        int kp = it + STAGES - 1;
        if (kp < niter) load_stage(kp * 16, kp % STAGES);
        cp_commit();
        cp_wait<STAGES - 1>();
        __syncthreads();

        int st = it % STAGES;
        const float* Asm = sm + st * STG_W;
        const float* Bsm = Asm + ASZ;

        #pragma unroll
        for (int kk = 0; kk < 2; kk++) {
            int kb = kk * 8;
            uint32_t af[2][4];
            uint32_t bfr[8][2];
            if (TRANSB) {
                #pragma unroll
                for (int im = 0; im < 2; im++) {
                    int r = wm + im * 16 + lr;
                    uint2 v0 = *(const uint2*)&Asm[r * ASTR + kb + 2 * lc];
                    uint2 v1 = *(const uint2*)&Asm[(r + 8) * ASTR + kb + 2 * lc];
                    af[im][0] = v0.x; af[im][1] = v1.x;
                    af[im][2] = v0.y; af[im][3] = v1.y;
                }
                #pragma unroll
                for (int in_ = 0; in_ < 8; in_++) {
                    int nn = wn + in_ * 8 + lr;
                    uint2 w = *(const uint2*)&Bsm[nn * ASTR + kb + 2 * lc];
                    bfr[in_][0] = w.x; bfr[in_][1] = w.y;
                }
            } else {
                const uint32_t* Au = (const uint32_t*)Asm;
                const uint32_t* Bu = (const uint32_t*)Bsm;
                #pragma unroll
                for (int im = 0; im < 2; im++) {
                    int r = wm + im * 16 + lr;
                    af[im][0] = Au[r * ASTR + kb + lc];
                    af[im][1] = Au[(r + 8) * ASTR + kb + lc];
                    af[im][2] = Au[r * ASTR + kb + lc + 4];
                    af[im][3] = Au[(r + 8) * ASTR + kb + lc + 4];
                }
                #pragma unroll
                for (int in_ = 0; in_ < 8; in_++) {
                    int nn = wn + in_ * 8 + lr;
                    bfr[in_][0] = Bu[(kb + lc) * BSTRN + nn];
                    bfr[in_][1] = Bu[(kb + lc + 4) * BSTRN + nn];
                }
            }
            #pragma unroll
            for (int im = 0; im < 2; im++)
                #pragma unroll
                for (int in_ = 0; in_ < 8; in_++)
                    mma_tf32(acc[im][in_], af[im], bfr[in_]);
        }
        __syncthreads();
    }

    if (resid) resid += (long)z * sR;
    gemm_epilogue(acc, C, M, N, ldc, m0, n0, wm, wn, lr, lc, biasM, biasN, resid, act);
}

// ---------------- host side --------------------------------------------------
static void launch_gemm(const float* A, const float* B, float* C,
                        int M, int N, int K, int lda, int ldb, int ldc,
                        long sA, long sB, long sC, int batch, int transB,
                        const float* biasM, const float* biasN,
                        const float* resid, long sR, int act) {
    dim3 grid((N + 127) / 128, (M + 127) / 128, batch);
    if (transB) {
        cudaFuncSetAttribute(gemm_tf32_pipe<1>,
                             cudaFuncAttributeMaxDynamicSharedMemorySize, PIPE_SMEM);
        gemm_tf32_pipe<1><<<grid, 256, PIPE_SMEM>>>(A, B, C, M, N, K, lda, ldb, ldc,
                                                    sA, sB, sC, biasM, biasN,
                                                    resid, sR, act);
    } else {
        cudaFuncSetAttribute(gemm_tf32_pipe<0>,
                             cudaFuncAttributeMaxDynamicSharedMemorySize, PIPE_SMEM);
        gemm_tf32_pipe<0><<<grid, 256, PIPE_SMEM>>>(A, B, C, M, N, K, lda, ldb, ldc,
                                                    sA, sB, sC, biasM, biasN,
                                                    resid, sR, act);
    }
}

extern "C" void kernel_launch(void* const* d_in, const int* in_sizes, int n_in,
                              void* d_out, int out_size) {
    const float* x       = (const float*)d_in[0];
    const float* bn1_g   = (const float*)d_in[1];
    const float* bn1_b   = (const float*)d_in[2];
    const float* conv1_w = (const float*)d_in[3];
    const float* conv1_b = (const float*)d_in[4];
    const float* ln_w    = (const float*)d_in[5];
    const float* ln_b    = (const float*)d_in[6];
    const float* W_in    = (const float*)d_in[7];
    const float* convm_w = (const float*)d_in[8];
    const float* convm_b = (const float*)d_in[9];
    const float* W_x     = (const float*)d_in[10];
    const float* W_dt    = (const float*)d_in[11];
    const float* b_dt    = (const float*)d_in[12];
    const float* A_log   = (const float*)d_in[13];
    const float* D_p     = (const float*)d_in[14];
    const float* W_out   = (const float*)d_in[15];
    const float* bn3_g   = (const float*)d_in[16];
    const float* bn3_b   = (const float*)d_in[17];
    const float* conv3_w = (const float*)d_in[18];
    const float* conv3_b = (const float*)d_in[19];
    float* out = (float*)d_out;

    float *pm1, *pr1, *pcm1, *pcr1, *pmL, *prL, *pm3, *pr3, *pcm3, *pcr3;
    float *ph, *ph1, *poutn, *pxz, *pxc, *pxdbl, *pdt, *py, *pres;
    float *pwin, *pwout, *pwx, *pwdt, *pc1w, *pc3w;
    cudaGetSymbolAddress((void**)&pm1,  g_m1);
    cudaGetSymbolAddress((void**)&pr1,  g_r1);
    cudaGetSymbolAddress((void**)&pcm1, g_cm1);
    cudaGetSymbolAddress((void**)&pcr1, g_cr1);
    cudaGetSymbolAddress((void**)&pmL,  g_mL);
    cudaGetSymbolAddress((void**)&prL,  g_rL);
    cudaGetSymbolAddress((void**)&pm3,  g_m3);
    cudaGetSymbolAddress((void**)&pr3,  g_r3);
    cudaGetSymbolAddress((void**)&pcm3, g_cm3);
    cudaGetSymbolAddress((void**)&pcr3, g_cr3);
    cudaGetSymbolAddress((void**)&ph,    g_h);
    cudaGetSymbolAddress((void**)&ph1,   g_h1);
    cudaGetSymbolAddress((void**)&poutn, g_outn);
    cudaGetSymbolAddress((void**)&pxz,   g_xz);
    cudaGetSymbolAddress((void**)&pxc,   g_xc);
    cudaGetSymbolAddress((void**)&pxdbl, g_xdbl);
    cudaGetSymbolAddress((void**)&pdt,   g_dt);
    cudaGetSymbolAddress((void**)&py,    g_y);
    cudaGetSymbolAddress((void**)&pres,  g_res);
    cudaGetSymbolAddress((void**)&pwin,  g_win);
    cudaGetSymbolAddress((void**)&pwout, g_wout);
    cudaGetSymbolAddress((void**)&pwx,   g_wx);
    cudaGetSymbolAddress((void**)&pwdt,  g_wdt);
    cudaGetSymbolAddress((void**)&pc1w,  g_c1w);
    cudaGetSymbolAddress((void**)&pc3w,  g_c3w);

    const int EW_BLK = 256;
    const size_t nBCN4 = (size_t)ROWS * (NDIM / 4);
    int gBCN4 = (int)((nBCN4 + EW_BLK - 1) / EW_BLK);
    const size_t nBLD4 = (size_t)ROWS * (DIX / 4);
    int gBLD4 = (int)((nBLD4 + EW_BLK - 1) / EW_BLK);

    // ---- pre-round weights to tf32 ----
    round_tf32_kernel<<<1024, 256>>>(W_in,  pwin,  (long)DIN2 * NDIM / 4);
    round_tf32_kernel<<<1024, 256>>>(W_out, pwout, (long)NDIM * DIX / 4);
    round_tf32_kernel<<<256,  256>>>(W_x,   pwx,   (long)XCOLS * DIX / 4);
    round_tf32_kernel<<<16,   256>>>(conv1_w, pc1w, (long)CCH * CCH / 4);
    round_tf32_kernel<<<16,   256>>>(conv3_w, pc3w, (long)CCH * CCH / 4);
    round_pad_wdt<<<(DIX * 128 + 255) / 256, 256>>>(W_dt, pwdt);

    // ---- Block 1: inorm -> bnorm -> relu -> 1x1 conv ----
    rowstat_kernel<<<ROWS, 256>>>(x, pm1, pr1, 1e-3f);
    chanstat_kernel<<<CCH, 256>>>(x, pm1, pr1, pcm1, pcr1, 1e-5f);
    normrelu_kernel<<<gBCN4, EW_BLK>>>(x, pm1, pr1, pcm1, pcr1, bn1_g, bn1_b, ph);
    launch_gemm(pc1w, ph, ph1, CCH, NDIM, CCH, CCH, NDIM, NDIM,
                0, (long)CCH * NDIM, (long)CCH * NDIM, BATCH, 0,
                conv1_b, nullptr, nullptr, 0, 0);

    // ---- LayerNorm over N ----
    rowstat_kernel<<<ROWS, 256>>>(ph1, pmL, prL, 1e-5f);
    lnapply_kernel<<<gBCN4, EW_BLK>>>(ph1, pmL, prL, ln_w, ln_b, poutn);

    // ---- Mamba ----
    launch_gemm(poutn, pwin, pxz, ROWS, DIN2, NDIM, NDIM, NDIM, DIN2,
                0, 0, 0, 1, 1, nullptr, nullptr, nullptr, 0, 0);
    convm_silu_kernel<<<gBLD4, EW_BLK>>>(pxz, convm_w, convm_b, pxc);
    launch_gemm(pxc, pwx, pxdbl, ROWS, XCOLS, DIX, DIX, DIX, XSTR,
                0, 0, 0, 1, 1, nullptr, nullptr, nullptr, 0, 0);
    launch_gemm(pxdbl, pwdt, pdt, ROWS, DIX, 128, XSTR, 128, DIX,
                0, 0, 0, 1, 1, nullptr, b_dt, nullptr, 0, 2);
    scan_kernel<<<(BATCH * DIX + 255) / 256, 256>>>(pdt, pxc, pxdbl, pxz,
                                                    A_log, D_p, py);
    launch_gemm(py, pwout, pres, ROWS, NDIM, DIX, DIX, DIX, NDIM,
                0, 0, 0, 1, 1, nullptr, nullptr, ph1, 0, 0);

    // ---- Block 3 ----
    rowstat_kernel<<<ROWS, 256>>>(pres, pm3, pr3, 1e-3f);
    chanstat_kernel<<<CCH, 256>>>(pres, pm3, pr3, pcm3, pcr3, 1e-5f);
    normrelu_kernel<<<gBCN4, EW_BLK>>>(pres, pm3, pr3, pcm3, pcr3, bn3_g, bn3_b, ph);
    launch_gemm(pc3w, ph, out, CCH, NDIM, CCH, CCH, NDIM, NDIM,
                0, (long)CCH * NDIM, (long)CCH * NDIM, BATCH, 0,
                conv3_b, nullptr, x, (long)CCH * NDIM, 0);
}

// round 14
// speedup vs baseline: 2.2235x; 1.5161x over previous
#include <cuda_runtime.h>
#include <cuda_fp16.h>
#include <math.h>
#include <stdint.h>

#define BATCH 16
#define CCH   128
#define NDIM  2000
#define SST   8
#define DCONVK 4
#define DIX   4000
#define DTR   125
#define XCOLS 141     // DTR + 2*SST
#define XSTR  144     // padded xdbl row stride
#define LSEQ  128
#define ROWS  2048
#define DIN2  8000

// ---------------- scratch (static device memory; no allocations) -------------
__device__ float g_m1[ROWS], g_r1[ROWS];
__device__ float g_cm1[CCH], g_cr1[CCH];
__device__ float g_mL[ROWS], g_rL[ROWS];
__device__ float g_m3[ROWS], g_r3[ROWS];
__device__ float g_cm3[CCH], g_cr3[CCH];
__device__ __align__(16) float g_h   [(size_t)ROWS*NDIM];
__device__ __align__(16) float g_h1  [(size_t)ROWS*NDIM];
__device__ __align__(16) float g_res [(size_t)ROWS*NDIM];
// half activations
__device__ __align__(16) __half g_outnh[(size_t)ROWS*NDIM];
__device__ __align__(16) __half g_xzh  [(size_t)ROWS*DIN2];
__device__ __align__(16) __half g_xch  [(size_t)ROWS*DIX];
__device__ __align__(16) __half g_xdblh[(size_t)ROWS*XSTR];
__device__ __align__(16) __half g_dth  [(size_t)ROWS*DIX];
__device__ __align__(16) __half g_yh   [(size_t)ROWS*DIX];
// half weights
__device__ __align__(16) __half g_winh [(size_t)DIN2*NDIM];
__device__ __align__(16) __half g_wouth[(size_t)NDIM*DIX];
__device__ __align__(16) __half g_wxh  [(size_t)XCOLS*DIX];
__device__ __align__(16) __half g_wdth [(size_t)DIX*128];
// tf32 conv weights
__device__ __align__(16) float g_c1w [CCH*CCH];
__device__ __align__(16) float g_c3w [CCH*CCH];

__device__ __forceinline__ uint32_t f2tf(float x) {
    uint32_t r;
    asm("cvt.rna.tf32.f32 %0, %1;" : "=r"(r) : "f"(x));
    return r;
}
__device__ __forceinline__ float rtf(float x) { return __uint_as_float(f2tf(x)); }

// ---------------- reductions -------------------------------------------------
__device__ __forceinline__ void block_reduce2(float& s, float& s2) {
    __shared__ float sh[16];
    #pragma unroll
    for (int o = 16; o; o >>= 1) {
        s  += __shfl_down_sync(0xffffffffu, s,  o);
        s2 += __shfl_down_sync(0xffffffffu, s2, o);
    }
    int w = threadIdx.x >> 5, lane = threadIdx.x & 31;
    if (lane == 0) { sh[w] = s; sh[8 + w] = s2; }
    __syncthreads();
    if (threadIdx.x == 0) {
        float S = 0.f, S2 = 0.f;
        int nw = blockDim.x >> 5;
        for (int i = 0; i < nw; i++) { S += sh[i]; S2 += sh[8 + i]; }
        sh[0] = S; sh[8] = S2;
    }
    __syncthreads();
    s = sh[0]; s2 = sh[8];
}

__global__ void rowstat_kernel(const float* __restrict__ x, float* __restrict__ mean,
                               float* __restrict__ rstd, float eps) {
    int row = blockIdx.x;
    const float4* p = (const float4*)(x + (size_t)row * NDIM);
    float s = 0.f, s2 = 0.f;
    for (int i = threadIdx.x; i < NDIM / 4; i += blockDim.x) {
        float4 v = p[i];
        s  += v.x + v.y + v.z + v.w;
        s2 += v.x * v.x + v.y * v.y + v.z * v.z + v.w * v.w;
    }
    block_reduce2(s, s2);
    if (threadIdx.x == 0) {
        float m = s / NDIM;
        float var = s2 / NDIM - m * m;
        mean[row] = m;
        rstd[row] = rsqrtf(var + eps);
    }
}

__global__ void chanstat_kernel(const float* __restrict__ x, const float* __restrict__ m,
                                const float* __restrict__ r, float* __restrict__ cmean,
                                float* __restrict__ crstd, float eps) {
    int c = blockIdx.x;
    const float4* x4 = (const float4*)x;
    float s = 0.f, s2 = 0.f;
    for (int idx = threadIdx.x; idx < BATCH * (NDIM / 4); idx += blockDim.x) {
        int b = idx / (NDIM / 4), n4 = idx - b * (NDIM / 4);
        int row = b * CCH + c;
        float mm = m[row], rr = r[row];
        float4 v = x4[(size_t)row * (NDIM / 4) + n4];
        float a0 = (v.x - mm) * rr, a1 = (v.y - mm) * rr;
        float a2 = (v.z - mm) * rr, a3 = (v.w - mm) * rr;
        s  += a0 + a1 + a2 + a3;
        s2 += a0 * a0 + a1 * a1 + a2 * a2 + a3 * a3;
    }
    block_reduce2(s, s2);
    if (threadIdx.x == 0) {
        float mm = s / (BATCH * NDIM);
        float var = s2 / (BATCH * NDIM) - mm * mm;
        cmean[c] = mm;
        crstd[c] = rsqrtf(var + eps);
    }
}

__global__ void normrelu_kernel(const float* __restrict__ x, const float* __restrict__ m,
                                const float* __restrict__ r, const float* __restrict__ cm,
                                const float* __restrict__ cr, const float* __restrict__ g,
                                const float* __restrict__ bb, float* __restrict__ out) {
    size_t i = (size_t)blockIdx.x * blockDim.x + threadIdx.x;
    if (i >= (size_t)ROWS * (NDIM / 4)) return;
    int row = (int)(i / (NDIM / 4));
    int c = row & (CCH - 1);
    float a = r[row] * cr[c] * g[c];
    float d = (-m[row]) * a + (-cm[c]) * cr[c] * g[c] + bb[c];
    float4 v = ((const float4*)x)[i];
    float4 o;
    o.x = rtf(fmaxf(v.x * a + d, 0.f));
    o.y = rtf(fmaxf(v.y * a + d, 0.f));
    o.z = rtf(fmaxf(v.z * a + d, 0.f));
    o.w = rtf(fmaxf(v.w * a + d, 0.f));
    ((float4*)out)[i] = o;
}

// layernorm apply -> half output (fp16 GEMM operand)
__global__ void lnapply_h_kernel(const float* __restrict__ x, const float* __restrict__ m,
                                 const float* __restrict__ r, const float* __restrict__ w,
                                 const float* __restrict__ bb, __half* __restrict__ out) {
    size_t i = (size_t)blockIdx.x * blockDim.x + threadIdx.x;
    if (i >= (size_t)ROWS * (NDIM / 4)) return;
    int row = (int)(i / (NDIM / 4));
    int n4 = (int)(i - (size_t)row * (NDIM / 4));
    float mm = m[row], rr = r[row];
    float4 v = ((const float4*)x)[i];
    float4 wv = ((const float4*)w)[n4];
    float4 bv = ((const float4*)bb)[n4];
    __half2 o0 = __floats2half2_rn((v.x - mm) * rr * wv.x + bv.x,
                                   (v.y - mm) * rr * wv.y + bv.y);
    __half2 o1 = __floats2half2_rn((v.z - mm) * rr * wv.z + bv.z,
                                   (v.w - mm) * rr * wv.w + bv.w);
    ((__half2*)out)[i * 2 + 0] = o0;
    ((__half2*)out)[i * 2 + 1] = o1;
}

// depthwise causal conv + silu; half in/out, fp32 math
__global__ void convm_silu_h_kernel(const __half* __restrict__ xz,
                                    const float* __restrict__ cw,
                                    const float* __restrict__ cb,
                                    __half* __restrict__ xc) {
    size_t i = (size_t)blockIdx.x * blockDim.x + threadIdx.x;   // (mrow, d4)
    if (i >= (size_t)ROWS * (DIX / 4)) return;
    int d4 = (int)(i % (DIX / 4));
    size_t mrow = i / (DIX / 4);
    int l = (int)(mrow & (LSEQ - 1));
    size_t b = mrow >> 7;
    int d = d4 * 4;
    float4 acc = ((const float4*)cb)[d4];
    float4 w0 = ((const float4*)cw)[d + 0];
    float4 w1 = ((const float4*)cw)[d + 1];
    float4 w2 = ((const float4*)cw)[d + 2];
    float4 w3 = ((const float4*)cw)[d + 3];
    #pragma unroll
    for (int k = 0; k < DCONVK; k++) {
        int ls = l + k - (DCONVK - 1);
        if (ls >= 0) {
            const __half2* p = (const __half2*)(xz + (b * LSEQ + ls) * (size_t)DIN2 + d);
            float2 v01 = __half22float2(p[0]);
            float2 v23 = __half22float2(p[1]);
            acc.x += v01.x * (&w0.x)[k];
            acc.y += v01.y * (&w1.x)[k];
            acc.z += v23.x * (&w2.x)[k];
            acc.w += v23.y * (&w3.x)[k];
        }
    }
    __half2 o0 = __floats2half2_rn(acc.x * (1.f / (1.f + __expf(-acc.x))),
                                   acc.y * (1.f / (1.f + __expf(-acc.y))));
    __half2 o1 = __floats2half2_rn(acc.z * (1.f / (1.f + __expf(-acc.z))),
                                   acc.w * (1.f / (1.f + __expf(-acc.w))));
    ((__half2*)xc)[i * 2 + 0] = o0;
    ((__half2*)xc)[i * 2 + 1] = o1;
}

// selective scan, half in/out, fp32 state
__global__ void scan_h_kernel(const __half* __restrict__ dt, const __half* __restrict__ xc,
                              const __half* __restrict__ xdbl, const __half* __restrict__ xz,
                              const float* __restrict__ A_log, const float* __restrict__ D_p,
                              __half* __restrict__ y) {
    int gidx = blockIdx.x * blockDim.x + threadIdx.x;
    if (gidx >= BATCH * DIX) return;
    int b = gidx / DIX, d = gidx - b * DIX;
    float A[SST], h[SST];
    #pragma unroll
    for (int s = 0; s < SST; s++) {
        A[s] = -expf(A_log[d * SST + s]);
        h[s] = 0.f;
    }
    float Dp = D_p[d];
    for (int l = 0; l < LSEQ; l++) {
        size_t m = (size_t)b * LSEQ + l;
        float dtv = __half2float(dt[m * DIX + d]);
        float u = __half2float(xc[m * DIX + d]);
        float du = dtv * u;
        const __half* xr = xdbl + m * XSTR;
        float yv = 0.f;
        #pragma unroll
        for (int s = 0; s < SST; s++) {
            h[s] = __expf(dtv * A[s]) * h[s] + du * __half2float(xr[DTR + s]);
            yv += h[s] * __half2float(xr[DTR + SST + s]);
        }
        float zv = __half2float(xz[m * DIN2 + DIX + d]);
        y[m * DIX + d] = __float2half_rn((yv + u * Dp) * (zv / (1.f + __expf(-zv))));
    }
}

// float -> half (groups of 4)
__global__ void round_half_kernel(const float* __restrict__ src, __half* __restrict__ dst,
                                  long n4) {
    long i = (long)blockIdx.x * blockDim.x + threadIdx.x;
    long stride = (long)gridDim.x * blockDim.x;
    for (; i < n4; i += stride) {
        float4 v = ((const float4*)src)[i];
        ((__half2*)dst)[i * 2 + 0] = __floats2half2_rn(v.x, v.y);
        ((__half2*)dst)[i * 2 + 1] = __floats2half2_rn(v.z, v.w);
    }
}

// float -> tf32 (conv weights)
__global__ void round_tf32_kernel(const float* __restrict__ src, float* __restrict__ dst,
                                  long n4) {
    long i = (long)blockIdx.x * blockDim.x + threadIdx.x;
    long stride = (long)gridDim.x * blockDim.x;
    for (; i < n4; i += stride) {
        float4 v = ((const float4*)src)[i];
        float4 o;
        o.x = rtf(v.x); o.y = rtf(v.y); o.z = rtf(v.z); o.w = rtf(v.w);
        ((float4*)dst)[i] = o;
    }
}

// W_dt [DIX,125] -> half padded [DIX,128]
__global__ void round_pad_wdt_h(const float* __restrict__ src, __half* __restrict__ dst) {
    int i = blockIdx.x * blockDim.x + threadIdx.x;
    if (i >= DIX * 128) return;
    int d = i >> 7, r = i & 127;
    dst[i] = __float2half_rn((r < DTR) ? src[d * DTR + r] : 0.f);
}

// ---------------- common async helpers ---------------------------------------
__device__ __forceinline__ void cpa16(uint32_t dst, const void* src, bool pred) {
    int sz = pred ? 16 : 0;
    asm volatile("cp.async.cg.shared.global [%0], [%1], 16, %2;\n"
                 :: "r"(dst), "l"(src), "r"(sz));
}
__device__ __forceinline__ void cp_commit() {
    asm volatile("cp.async.commit_group;\n");
}
template <int n>
__device__ __forceinline__ void cp_wait() {
    asm volatile("cp.async.wait_group %0;\n" :: "n"(n));
}

// ============================================================================
// FP16 transB GEMM: C[m,n] = sum_k A[m,k]*B[n,k]; A,B half, C half or float.
// 128x128 tile, BK=16 halfs, 4-stage cp.async, ldmatrix fragments.
// ============================================================================
#define HSTR_B 48                      // smem row stride bytes (16 halfs + 8 pad)
#define HTILE  (128 * HSTR_B)          // 6144 B per operand tile
#define HSTG   (2 * HTILE)             // 12288 B per stage
#define HSTAGES 4
#define H_SMEM (HSTAGES * HSTG)        // 49152 B

__device__ __forceinline__ void ldsm4(uint32_t& r0, uint32_t& r1, uint32_t& r2,
                                      uint32_t& r3, uint32_t addr) {
    asm volatile("ldmatrix.sync.aligned.m8n8.x4.shared.b16 {%0,%1,%2,%3}, [%4];"
                 : "=r"(r0), "=r"(r1), "=r"(r2), "=r"(r3) : "r"(addr));
}

__device__ __forceinline__ void mma_f16(float* c, const uint32_t* a, const uint32_t* b) {
    asm volatile(
        "mma.sync.aligned.m16n8k16.row.col.f32.f16.f16.f32 "
        "{%0,%1,%2,%3}, {%4,%5,%6,%7}, {%8,%9}, {%0,%1,%2,%3};\n"
        : "+f"(c[0]), "+f"(c[1]), "+f"(c[2]), "+f"(c[3])
        : "r"(a[0]), "r"(a[1]), "r"(a[2]), "r"(a[3]), "r"(b[0]), "r"(b[1]));
}

template <int OUTHALF>
__global__ void __launch_bounds__(256, 2) gemm_f16_pipe(
    const __half* __restrict__ A, const __half* __restrict__ Bp, void* __restrict__ Cv,
    int M, int N, int K, int lda, int ldb, int ldc,
    const float* __restrict__ biasN, const float* __restrict__ resid, int act) {
    extern __shared__ char hsm[];
    uint32_t smbase = (uint32_t)__cvta_generic_to_shared(hsm);

    int m0 = blockIdx.y * 128, n0 = blockIdx.x * 128;
    int tid = threadIdx.x;
    int warp = tid >> 5, lane = tid & 31;
    int wm = (warp >> 1) * 32;
    int wn = (warp & 1) * 64;
    int lr = lane >> 2, lc = lane & 3;

    float acc[2][8][4];
    #pragma unroll
    for (int i = 0; i < 2; i++)
        #pragma unroll
        for (int j = 0; j < 8; j++)
            #pragma unroll
            for (int q = 0; q < 4; q++) acc[i][j][q] = 0.f;

    // per-lane ldmatrix offsets (bytes within a tile)
    int q = lane >> 3, rr = lane & 7;
    // A: q0:(rr,k0) q1:(rr+8,k0) q2:(rr,k8) q3:(rr+8,k8)
    uint32_t aLane = (uint32_t)((((q == 1 || q == 3) ? 8 : 0) + rr) * HSTR_B +
                                ((q >= 2) ? 16 : 0));
    // B: q0:(rr,k0) q1:(rr,k8) q2:(rr+8,k0) q3:(rr+8,k8)
    uint32_t bLane = (uint32_t)((((q >= 2) ? 8 : 0) + rr) * HSTR_B +
                                ((q & 1) ? 16 : 0));

    int lrow = tid >> 1, lseg = tid & 1;

    auto load_stage = [&](int k0, int st) {
        uint32_t ab = smbase + (uint32_t)(st * HSTG);
        uint32_t bb = ab + HTILE;
        cpa16(ab + (uint32_t)(lrow * HSTR_B + lseg * 16),
              A + (long)(m0 + lrow) * lda + k0 + lseg * 8, (m0 + lrow) < M);
        cpa16(bb + (uint32_t)(lrow * HSTR_B + lseg * 16),
              Bp + (long)(n0 + lrow) * ldb + k0 + lseg * 8, (n0 + lrow) < N);
    };

    int niter = K >> 4;

    #pragma unroll
    for (int s = 0; s < HSTAGES - 1; s++) {
        load_stage(s * 16, s);
        cp_commit();
    }

    for (int it = 0; it < niter; it++) {
        int kp = it + HSTAGES - 1;
        if (kp < niter) load_stage(kp * 16, kp % HSTAGES);
        cp_commit();
        cp_wait<HSTAGES - 1>();
        __syncthreads();

        int st = it % HSTAGES;
        uint32_t ab = smbase + (uint32_t)(st * HSTG);
        uint32_t bb = ab + HTILE;

        uint32_t af[2][4];
        #pragma unroll
        for (int im = 0; im < 2; im++)
            ldsm4(af[im][0], af[im][1], af[im][2], af[im][3],
                  ab + (uint32_t)((wm + im * 16) * HSTR_B) + aLane);
        uint32_t bf[4][4];
        #pragma unroll
        for (int j = 0; j < 4; j++)
            ldsm4(bf[j][0], bf[j][1], bf[j][2], bf[j][3],
                  bb + (uint32_t)((wn + j * 16) * HSTR_B) + bLane);

        #pragma unroll
        for (int im = 0; im < 2; im++)
            #pragma unroll
            for (int j = 0; j < 4; j++) {
                uint32_t blo[2] = { bf[j][0], bf[j][1] };
                uint32_t bhi[2] = { bf[j][2], bf[j][3] };
                mma_f16(acc[im][2 * j + 0], af[im], blo);
                mma_f16(acc[im][2 * j + 1], af[im], bhi);
            }
        __syncthreads();
    }

    // ---- epilogue ----
    #pragma unroll
    for (int im = 0; im < 2; im++) {
        #pragma unroll
        for (int rr2 = 0; rr2 < 2; rr2++) {
            int gm = m0 + wm + im * 16 + lr + rr2 * 8;
            if (gm >= M) continue;
            #pragma unroll
            for (int in_ = 0; in_ < 8; in_++) {
                int gn = n0 + wn + in_ * 8 + 2 * lc;
                float v0 = acc[im][in_][rr2 * 2 + 0];
                float v1 = acc[im][in_][rr2 * 2 + 1];
                if (biasN) {
                    if (gn + 0 < N) v0 += biasN[gn + 0];
                    if (gn + 1 < N) v1 += biasN[gn + 1];
                }
                if (resid) {
                    if (gn + 0 < N) v0 += resid[(long)gm * ldc + gn + 0];
                    if (gn + 1 < N) v1 += resid[(long)gm * ldc + gn + 1];
                }
                if (act == 2) {
                    v0 = fmaxf(v0, 0.f) + __logf(1.f + __expf(-fabsf(v0)));
                    v1 = fmaxf(v1, 0.f) + __logf(1.f + __expf(-fabsf(v1)));
                }
                if (OUTHALF) {
                    __half* cp = (__half*)Cv + (long)gm * ldc + gn;
                    if (gn + 1 < N) {
                        *(__half2*)cp = __floats2half2_rn(v0, v1);
                    } else if (gn < N) {
                        cp[0] = __float2half_rn(v0);
                    }
                } else {
                    float* cp = (float*)Cv + (long)gm * ldc + gn;
                    if (gn + 1 < N && ((((uintptr_t)cp) & 7) == 0)) {
                        *(float2*)cp = make_float2(v0, v1);
                    } else {
                        if (gn + 0 < N) cp[0] = v0;
                        if (gn + 1 < N) cp[1] = v1;
                    }
                }
            }
        }
    }
}

// ============================================================================
// TF32 notrans GEMM (conv1/conv3): C = A[k-major] * B[k,n], batched over z
// ============================================================================
#define ASTRN 20
#define BSTRN 136
#define TSTAGES 4
#define TASZ   3072
#define TBSZ   3072
#define TSTG_W (TASZ + TBSZ)
#define T_SMEM (TSTAGES * TSTG_W * 4)

__device__ __forceinline__ void mma_tf32(float* c, const uint32_t* a, const uint32_t* b) {
    asm volatile(
        "mma.sync.aligned.m16n8k8.row.col.f32.tf32.tf32.f32 "
        "{%0,%1,%2,%3}, {%4,%5,%6,%7}, {%8,%9}, {%0,%1,%2,%3};\n"
        : "+f"(c[0]), "+f"(c[1]), "+f"(c[2]), "+f"(c[3])
        : "r"(a[0]), "r"(a[1]), "r"(a[2]), "r"(a[3]), "r"(b[0]), "r"(b[1]));
}

__global__ void __launch_bounds__(256, 2) gemm_tf32_conv(
    const float* __restrict__ A, const float* __restrict__ Bp, float* __restrict__ C,
    int M, int N, int K, int lda, int ldb, int ldc,
    long sB, long sC,
    const float* __restrict__ biasM, const float* __restrict__ resid, long sR) {
    extern __shared__ float sm[];
    uint32_t smbase = (uint32_t)__cvta_generic_to_shared(sm);

    int z = blockIdx.z;
    Bp += (long)z * sB;
    C  += (long)z * sC;

    int m0 = blockIdx.y * 128, n0 = blockIdx.x * 128;
    int tid = threadIdx.x;
    int warp = tid >> 5, lane = tid & 31;
    int wm = (warp >> 1) * 32;
    int wn = (warp & 1) * 64;
    int lr = lane >> 2, lc = lane & 3;

    float acc[2][8][4];
    #pragma unroll
    for (int i = 0; i < 2; i++)
        #pragma unroll
        for (int j = 0; j < 8; j++)
            #pragma unroll
            for (int q = 0; q < 4; q++) acc[i][j][q] = 0.f;

    int a_row[2], a_c4[2];
    #pragma unroll
    for (int j = 0; j < 2; j++) {
        int f = tid + j * 256;
        a_row[j] = f >> 2;
        a_c4[j]  = (f & 3) * 4;
    }

    auto load_stage = [&](int k0, int st) {
        uint32_t abase = smbase + (uint32_t)(st * TSTG_W * 4);
        uint32_t bbase = abase + (uint32_t)(TASZ * 4);
        #pragma unroll
        for (int j = 0; j < 2; j++) {
            int row = a_row[j], c4 = a_c4[j];
            int gm = m0 + row;
            cpa16(abase + (uint32_t)((row * ASTRN + c4) * 4),
                  A + (long)gm * lda + k0 + c4, gm < M);
        }
        #pragma unroll
        for (int j = 0; j < 2; j++) {
            int f = tid + j * 256;
            int kk = f >> 5, n4 = (f & 31) * 4;
            int gn = n0 + n4;
            cpa16(bbase + (uint32_t)((kk * BSTRN + n4) * 4),
                  Bp + (long)(k0 + kk) * ldb + gn, gn < N);
        }
    };

    int niter = K >> 4;

    #pragma unroll
    for (int s = 0; s < TSTAGES - 1; s++) {
        load_stage(s * 16, s);
        cp_commit();
    }

    for (int it = 0; it < niter; it++) {
        int kp = it + TSTAGES - 1;
        if (kp < niter) load_stage(kp * 16, kp % TSTAGES);
        cp_commit();
        cp_wait<TSTAGES - 1>();
        __syncthreads();

        int st = it % TSTAGES;
        const float* Asm = sm + st * TSTG_W;
        const float* Bsm = Asm + TASZ;
        const uint32_t* Au = (const uint32_t*)Asm;
        const uint32_t* Bu = (const uint32_t*)Bsm;

        #pragma unroll
        for (int kk = 0; kk < 2; kk++) {
            int kb = kk * 8;
            uint32_t af[2][4];
            uint32_t bfr[8][2];
            #pragma unroll
            for (int im = 0; im < 2; im++) {
                int r = wm + im * 16 + lr;
                af[im][0] = Au[r * ASTRN + kb + lc];
                af[im][1] = Au[(r + 8) * ASTRN + kb + lc];
                af[im][2] = Au[r * ASTRN + kb + lc + 4];
                af[im][3] = Au[(r + 8) * ASTRN + kb + lc + 4];
            }
            #pragma unroll
            for (int in_ = 0; in_ < 8; in_++) {
                int nn = wn + in_ * 8 + lr;
                bfr[in_][0] = Bu[(kb + lc) * BSTRN + nn];
                bfr[in_][1] = Bu[(kb + lc + 4) * BSTRN + nn];
            }
            #pragma unroll
            for (int im = 0; im < 2; im++)
                #pragma unroll
                for (int in_ = 0; in_ < 8; in_++)
                    mma_tf32(acc[im][in_], af[im], bfr[in_]);
        }
        __syncthreads();
    }

    if (resid) resid += (long)z * sR;
    #pragma unroll
    for (int im = 0; im < 2; im++) {
        #pragma unroll
        for (int rr = 0; rr < 2; rr++) {
            int gm = m0 + wm + im * 16 + lr + rr * 8;
            if (gm >= M) continue;
            float bm = biasM ? biasM[gm] : 0.f;
            #pragma unroll
            for (int in_ = 0; in_ < 8; in_++) {
                int gn = n0 + wn + in_ * 8 + 2 * lc;
                float v0 = acc[im][in_][rr * 2 + 0] + bm;
                float v1 = acc[im][in_][rr * 2 + 1] + bm;
                if (resid) {
                    if (gn + 0 < N) v0 += resid[(long)gm * ldc + gn + 0];
                    if (gn + 1 < N) v1 += resid[(long)gm * ldc + gn + 1];
                }
                float* cp = &C[(long)gm * ldc + gn];
                if (gn + 1 < N && ((((uintptr_t)cp) & 7) == 0)) {
                    *(float2*)cp = make_float2(v0, v1);
                } else {
                    if (gn + 0 < N) cp[0] = v0;
                    if (gn + 1 < N) cp[1] = v1;
                }
            }
        }
    }
}

// ---------------- host side --------------------------------------------------
static void launch_gemm_f16(const __half* A, const __half* B, void* C,
                            int M, int N, int K, int lda, int ldb, int ldc,
                            int outhalf, const float* biasN, const float* resid,
                            int act) {
    dim3 grid((N + 127) / 128, (M + 127) / 128, 1);
    if (outhalf) {
        cudaFuncSetAttribute(gemm_f16_pipe<1>,
                             cudaFuncAttributeMaxDynamicSharedMemorySize, H_SMEM);
        gemm_f16_pipe<1><<<grid, 256, H_SMEM>>>(A, B, C, M, N, K, lda, ldb, ldc,
                                                biasN, resid, act);
    } else {
        cudaFuncSetAttribute(gemm_f16_pipe<0>,
                             cudaFuncAttributeMaxDynamicSharedMemorySize, H_SMEM);
        gemm_f16_pipe<0><<<grid, 256, H_SMEM>>>(A, B, C, M, N, K, lda, ldb, ldc,
                                                biasN, resid, act);
    }
}

extern "C" void kernel_launch(void* const* d_in, const int* in_sizes, int n_in,
                              void* d_out, int out_size) {
    const float* x       = (const float*)d_in[0];
    const float* bn1_g   = (const float*)d_in[1];
    const float* bn1_b   = (const float*)d_in[2];
    const float* conv1_w = (const float*)d_in[3];
    const float* conv1_b = (const float*)d_in[4];
    const float* ln_w    = (const float*)d_in[5];
    const float* ln_b    = (const float*)d_in[6];
    const float* W_in    = (const float*)d_in[7];
    const float* convm_w = (const float*)d_in[8];
    const float* convm_b = (const float*)d_in[9];
    const float* W_x     = (const float*)d_in[10];
    const float* W_dt    = (const float*)d_in[11];
    const float* b_dt    = (const float*)d_in[12];
    const float* A_log   = (const float*)d_in[13];
    const float* D_p     = (const float*)d_in[14];
    const float* W_out   = (const float*)d_in[15];
    const float* bn3_g   = (const float*)d_in[16];
    const float* bn3_b   = (const float*)d_in[17];
    const float* conv3_w = (const float*)d_in[18];
    const float* conv3_b = (const float*)d_in[19];
    float* out = (float*)d_out;

    float *pm1, *pr1, *pcm1, *pcr1, *pmL, *prL, *pm3, *pr3, *pcm3, *pcr3;
    float *ph, *ph1, *pres, *pc1w, *pc3w;
    __half *poutnh, *pxzh, *pxch, *pxdblh, *pdth, *pyh;
    __half *pwinh, *pwouth, *pwxh, *pwdth;
    cudaGetSymbolAddress((void**)&pm1,  g_m1);
    cudaGetSymbolAddress((void**)&pr1,  g_r1);
    cudaGetSymbolAddress((void**)&pcm1, g_cm1);
    cudaGetSymbolAddress((void**)&pcr1, g_cr1);
    cudaGetSymbolAddress((void**)&pmL,  g_mL);
    cudaGetSymbolAddress((void**)&prL,  g_rL);
    cudaGetSymbolAddress((void**)&pm3,  g_m3);
    cudaGetSymbolAddress((void**)&pr3,  g_r3);
    cudaGetSymbolAddress((void**)&pcm3, g_cm3);
    cudaGetSymbolAddress((void**)&pcr3, g_cr3);
    cudaGetSymbolAddress((void**)&ph,    g_h);
    cudaGetSymbolAddress((void**)&ph1,   g_h1);
    cudaGetSymbolAddress((void**)&pres,  g_res);
    cudaGetSymbolAddress((void**)&poutnh, g_outnh);
    cudaGetSymbolAddress((void**)&pxzh,   g_xzh);
    cudaGetSymbolAddress((void**)&pxch,   g_xch);
    cudaGetSymbolAddress((void**)&pxdblh, g_xdblh);
    cudaGetSymbolAddress((void**)&pdth,   g_dth);
    cudaGetSymbolAddress((void**)&pyh,    g_yh);
    cudaGetSymbolAddress((void**)&pwinh,  g_winh);
    cudaGetSymbolAddress((void**)&pwouth, g_wouth);
    cudaGetSymbolAddress((void**)&pwxh,   g_wxh);
    cudaGetSymbolAddress((void**)&pwdth,  g_wdth);
    cudaGetSymbolAddress((void**)&pc1w,  g_c1w);
    cudaGetSymbolAddress((void**)&pc3w,  g_c3w);

    const int EW_BLK = 256;
    const size_t nBCN4 = (size_t)ROWS * (NDIM / 4);
    int gBCN4 = (int)((nBCN4 + EW_BLK - 1) / EW_BLK);
    const size_t nBLD4 = (size_t)ROWS * (DIX / 4);
    int gBLD4 = (int)((nBLD4 + EW_BLK - 1) / EW_BLK);

    // ---- weight conversion ----
    round_half_kernel<<<1024, 256>>>(W_in,  pwinh,  (long)DIN2 * NDIM / 4);
    round_half_kernel<<<1024, 256>>>(W_out, pwouth, (long)NDIM * DIX / 4);
    round_half_kernel<<<256,  256>>>(W_x,   pwxh,   (long)XCOLS * DIX / 4);
    round_tf32_kernel<<<16,   256>>>(conv1_w, pc1w, (long)CCH * CCH / 4);
    round_tf32_kernel<<<16,   256>>>(conv3_w, pc3w, (long)CCH * CCH / 4);
    round_pad_wdt_h<<<(DIX * 128 + 255) / 256, 256>>>(W_dt, pwdth);

    // ---- Block 1: inorm -> bnorm -> relu -> 1x1 conv (tf32) ----
    rowstat_kernel<<<ROWS, 256>>>(x, pm1, pr1, 1e-3f);
    chanstat_kernel<<<CCH, 256>>>(x, pm1, pr1, pcm1, pcr1, 1e-5f);
    normrelu_kernel<<<gBCN4, EW_BLK>>>(x, pm1, pr1, pcm1, pcr1, bn1_g, bn1_b, ph);
    {
        dim3 grid((NDIM + 127) / 128, 1, BATCH);
        cudaFuncSetAttribute(gemm_tf32_conv,
                             cudaFuncAttributeMaxDynamicSharedMemorySize, T_SMEM);
        gemm_tf32_conv<<<grid, 256, T_SMEM>>>(pc1w, ph, ph1, CCH, NDIM, CCH,
                                              CCH, NDIM, NDIM,
                                              (long)CCH * NDIM, (long)CCH * NDIM,
                                              conv1_b, nullptr, 0);
    }

    // ---- LayerNorm over N -> half ----
    rowstat_kernel<<<ROWS, 256>>>(ph1, pmL, prL, 1e-5f);
    lnapply_h_kernel<<<gBCN4, EW_BLK>>>(ph1, pmL, prL, ln_w, ln_b, poutnh);

    // ---- Mamba (fp16 GEMMs) ----
    launch_gemm_f16(poutnh, pwinh, pxzh, ROWS, DIN2, NDIM, NDIM, NDIM, DIN2,
                    1, nullptr, nullptr, 0);
    convm_silu_h_kernel<<<gBLD4, EW_BLK>>>(pxzh, convm_w, convm_b, pxch);
    launch_gemm_f16(pxch, pwxh, pxdblh, ROWS, XCOLS, DIX, DIX, DIX, XSTR,
                    1, nullptr, nullptr, 0);
    launch_gemm_f16(pxdblh, pwdth, pdth, ROWS, DIX, 128, XSTR, 128, DIX,
                    1, b_dt, nullptr, 2);
    scan_h_kernel<<<(BATCH * DIX + 255) / 256, 256>>>(pdth, pxch, pxdblh, pxzh,
                                                      A_log, D_p, pyh);
    launch_gemm_f16(pyh, pwouth, pres, ROWS, NDIM, DIX, DIX, DIX, NDIM,
                    0, nullptr, ph1, 0);

    // ---- Block 3 (tf32 conv + input residual) ----
    rowstat_kernel<<<ROWS, 256>>>(pres, pm3, pr3, 1e-3f);
    chanstat_kernel<<<CCH, 256>>>(pres, pm3, pr3, pcm3, pcr3, 1e-5f);
    normrelu_kernel<<<gBCN4, EW_BLK>>>(pres, pm3, pr3, pcm3, pcr3, bn3_g, bn3_b, ph);
    {
        dim3 grid((NDIM + 127) / 128, 1, BATCH);
        cudaFuncSetAttribute(gemm_tf32_conv,
                             cudaFuncAttributeMaxDynamicSharedMemorySize, T_SMEM);
        gemm_tf32_conv<<<grid, 256, T_SMEM>>>(pc3w, ph, out, CCH, NDIM, CCH,
                                              CCH, NDIM, NDIM,
                                              (long)CCH * NDIM, (long)CCH * NDIM,
                                              conv3_b, x, (long)CCH * NDIM);
    }
}

// round 17
// speedup vs baseline: 2.5869x; 1.1635x over previous
#include <cuda_runtime.h>
#include <cuda_fp16.h>
#include <math.h>
#include <stdint.h>

#define BATCH 16
#define CCH   128
#define NDIM  2000
#define SST   8
#define DCONVK 4
#define DIX   4000
#define DTR   125
#define XCOLS 141     // DTR + 2*SST
#define XSTR  144     // padded xdbl row stride
#define LSEQ  128
#define ROWS  2048
#define DIN2  8000
#define KSPLIT 4
#define KCHUNK 1024   // 1024,1024,1024,928 (all %16==0)

// ---------------- scratch (static device memory; no allocations) -------------
__device__ float g_m1[ROWS], g_r1[ROWS];
__device__ float g_cm1[CCH], g_cr1[CCH];
__device__ float g_mL[ROWS], g_rL[ROWS];
__device__ float g_m3[ROWS], g_r3[ROWS];
__device__ float g_cm3[CCH], g_cr3[CCH];
__device__ __align__(16) float g_h   [(size_t)ROWS*NDIM];
__device__ __align__(16) float g_h1  [(size_t)ROWS*NDIM];
__device__ __align__(16) float g_res [(size_t)ROWS*NDIM];
__device__ __align__(16) float g_xdbl4[(size_t)KSPLIT*ROWS*XSTR];
// half activations
__device__ __align__(16) __half g_outnh[(size_t)ROWS*NDIM];
__device__ __align__(16) __half g_xzh  [(size_t)ROWS*DIN2];
__device__ __align__(16) __half g_xch  [(size_t)ROWS*DIX];
__device__ __align__(16) __half g_xdblh[(size_t)ROWS*XSTR];
__device__ __align__(16) __half g_dth  [(size_t)ROWS*DIX];
__device__ __align__(16) __half g_yh   [(size_t)ROWS*DIX];
// half weights
__device__ __align__(16) __half g_winh [(size_t)DIN2*NDIM];
__device__ __align__(16) __half g_wouth[(size_t)NDIM*DIX];
__device__ __align__(16) __half g_wxh  [(size_t)XCOLS*DIX];
__device__ __align__(16) __half g_wdth [(size_t)DIX*128];
// tf32 conv weights
__device__ __align__(16) float g_c1w [CCH*CCH];
__device__ __align__(16) float g_c3w [CCH*CCH];

__device__ __forceinline__ uint32_t f2tf(float x) {
    uint32_t r;
    asm("cvt.rna.tf32.f32 %0, %1;" : "=r"(r) : "f"(x));
    return r;
}
__device__ __forceinline__ float rtf(float x) { return __uint_as_float(f2tf(x)); }

// ---------------- reductions -------------------------------------------------
__device__ __forceinline__ void block_reduce2(float& s, float& s2) {
    __shared__ float sh[16];
    #pragma unroll
    for (int o = 16; o; o >>= 1) {
        s  += __shfl_down_sync(0xffffffffu, s,  o);
        s2 += __shfl_down_sync(0xffffffffu, s2, o);
    }
    int w = threadIdx.x >> 5, lane = threadIdx.x & 31;
    if (lane == 0) { sh[w] = s; sh[8 + w] = s2; }
    __syncthreads();
    if (threadIdx.x == 0) {
        float S = 0.f, S2 = 0.f;
        int nw = blockDim.x >> 5;
        for (int i = 0; i < nw; i++) { S += sh[i]; S2 += sh[8 + i]; }
        sh[0] = S; sh[8] = S2;
    }
    __syncthreads();
    s = sh[0]; s2 = sh[8];
}

__global__ void rowstat_kernel(const float* __restrict__ x, float* __restrict__ mean,
                               float* __restrict__ rstd, float eps) {
    int row = blockIdx.x;
    const float4* p = (const float4*)(x + (size_t)row * NDIM);
    float s = 0.f, s2 = 0.f;
    for (int i = threadIdx.x; i < NDIM / 4; i += blockDim.x) {
        float4 v = p[i];
        s  += v.x + v.y + v.z + v.w;
        s2 += v.x * v.x + v.y * v.y + v.z * v.z + v.w * v.w;
    }
    block_reduce2(s, s2);
    if (threadIdx.x == 0) {
        float m = s / NDIM;
        float var = s2 / NDIM - m * m;
        mean[row] = m;
        rstd[row] = rsqrtf(var + eps);
    }
}

// analytic channel stats of instance-normed data:
// cmean = 0;  chan var = (1/B) sum_b (1 - eps_in * r_b^2)
__global__ void chanstat_fast(const float* __restrict__ rstd, float* __restrict__ cmean,
                              float* __restrict__ crstd, float eps_in, float eps_bn) {
    int c = threadIdx.x;
    if (c >= CCH) return;
    float s = 0.f;
    #pragma unroll
    for (int b = 0; b < BATCH; b++) {
        float rr = rstd[b * CCH + c];
        s += 1.f - eps_in * rr * rr;
    }
    cmean[c] = 0.f;
    crstd[c] = rsqrtf(s / BATCH + eps_bn);
}

__global__ void normrelu_kernel(const float* __restrict__ x, const float* __restrict__ m,
                                const float* __restrict__ r, const float* __restrict__ cm,
                                const float* __restrict__ cr, const float* __restrict__ g,
                                const float* __restrict__ bb, float* __restrict__ out) {
    size_t i = (size_t)blockIdx.x * blockDim.x + threadIdx.x;
    if (i >= (size_t)ROWS * (NDIM / 4)) return;
    int row = (int)(i / (NDIM / 4));
    int c = row & (CCH - 1);
    float a = r[row] * cr[c] * g[c];
    float d = (-m[row]) * a + (-cm[c]) * cr[c] * g[c] + bb[c];
    float4 v = ((const float4*)x)[i];
    float4 o;
    o.x = rtf(fmaxf(v.x * a + d, 0.f));
    o.y = rtf(fmaxf(v.y * a + d, 0.f));
    o.z = rtf(fmaxf(v.z * a + d, 0.f));
    o.w = rtf(fmaxf(v.w * a + d, 0.f));
    ((float4*)out)[i] = o;
}

__global__ void lnapply_h_kernel(const float* __restrict__ x, const float* __restrict__ m,
                                 const float* __restrict__ r, const float* __restrict__ w,
                                 const float* __restrict__ bb, __half* __restrict__ out) {
    size_t i = (size_t)blockIdx.x * blockDim.x + threadIdx.x;
    if (i >= (size_t)ROWS * (NDIM / 4)) return;
    int row = (int)(i / (NDIM / 4));
    int n4 = (int)(i - (size_t)row * (NDIM / 4));
    float mm = m[row], rr = r[row];
    float4 v = ((const float4*)x)[i];
    float4 wv = ((const float4*)w)[n4];
    float4 bv = ((const float4*)bb)[n4];
    __half2 o0 = __floats2half2_rn((v.x - mm) * rr * wv.x + bv.x,
                                   (v.y - mm) * rr * wv.y + bv.y);
    __half2 o1 = __floats2half2_rn((v.z - mm) * rr * wv.z + bv.z,
                                   (v.w - mm) * rr * wv.w + bv.w);
    ((__half2*)out)[i * 2 + 0] = o0;
    ((__half2*)out)[i * 2 + 1] = o1;
}

__global__ void convm_silu_h_kernel(const __half* __restrict__ xz,
                                    const float* __restrict__ cw,
                                    const float* __restrict__ cb,
                                    __half* __restrict__ xc) {
    size_t i = (size_t)blockIdx.x * blockDim.x + threadIdx.x;
    if (i >= (size_t)ROWS * (DIX / 4)) return;
    int d4 = (int)(i % (DIX / 4));
    size_t mrow = i / (DIX / 4);
    int l = (int)(mrow & (LSEQ - 1));
    size_t b = mrow >> 7;
    int d = d4 * 4;
    float4 acc = ((const float4*)cb)[d4];
    float4 w0 = ((const float4*)cw)[d + 0];
    float4 w1 = ((const float4*)cw)[d + 1];
    float4 w2 = ((const float4*)cw)[d + 2];
    float4 w3 = ((const float4*)cw)[d + 3];
    #pragma unroll
    for (int k = 0; k < DCONVK; k++) {
        int ls = l + k - (DCONVK - 1);
        if (ls >= 0) {
            const __half2* p = (const __half2*)(xz + (b * LSEQ + ls) * (size_t)DIN2 + d);
            float2 v01 = __half22float2(p[0]);
            float2 v23 = __half22float2(p[1]);
            acc.x += v01.x * (&w0.x)[k];
            acc.y += v01.y * (&w1.x)[k];
            acc.z += v23.x * (&w2.x)[k];
            acc.w += v23.y * (&w3.x)[k];
        }
    }
    __half2 o0 = __floats2half2_rn(acc.x * (1.f / (1.f + __expf(-acc.x))),
                                   acc.y * (1.f / (1.f + __expf(-acc.y))));
    __half2 o1 = __floats2half2_rn(acc.z * (1.f / (1.f + __expf(-acc.z))),
                                   acc.w * (1.f / (1.f + __expf(-acc.w))));
    ((__half2*)xc)[i * 2 + 0] = o0;
    ((__half2*)xc)[i * 2 + 1] = o1;
}

__global__ void scan_h_kernel(const __half* __restrict__ dt, const __half* __restrict__ xc,
                              const __half* __restrict__ xdbl, const __half* __restrict__ xz,
                              const float* __restrict__ A_log, const float* __restrict__ D_p,
                              __half* __restrict__ y) {
    int gidx = blockIdx.x * blockDim.x + threadIdx.x;
    if (gidx >= BATCH * DIX) return;
    int b = gidx / DIX, d = gidx - b * DIX;
    float A[SST], h[SST];
    #pragma unroll
    for (int s = 0; s < SST; s++) {
        A[s] = -expf(A_log[d * SST + s]);
        h[s] = 0.f;
    }
    float Dp = D_p[d];
    for (int l = 0; l < LSEQ; l++) {
        size_t m = (size_t)b * LSEQ + l;
        float dtv = __half2float(dt[m * DIX + d]);
        float u = __half2float(xc[m * DIX + d]);
        float du = dtv * u;
        const __half* xr = xdbl + m * XSTR;
        float yv = 0.f;
        #pragma unroll
        for (int s = 0; s < SST; s++) {
            h[s] = __expf(dtv * A[s]) * h[s] + du * __half2float(xr[DTR + s]);
            yv += h[s] * __half2float(xr[DTR + SST + s]);
        }
        float zv = __half2float(xz[m * DIN2 + DIX + d]);
        y[m * DIX + d] = __float2half_rn((yv + u * Dp) * (zv / (1.f + __expf(-zv))));
    }
}

__global__ void round_half_kernel(const float* __restrict__ src, __half* __restrict__ dst,
                                  long n4) {
    long i = (long)blockIdx.x * blockDim.x + threadIdx.x;
    long stride = (long)gridDim.x * blockDim.x;
    for (; i < n4; i += stride) {
        float4 v = ((const float4*)src)[i];
        ((__half2*)dst)[i * 2 + 0] = __floats2half2_rn(v.x, v.y);
        ((__half2*)dst)[i * 2 + 1] = __floats2half2_rn(v.z, v.w);
    }
}

__global__ void round_tf32_kernel(const float* __restrict__ src, float* __restrict__ dst,
                                  long n4) {
    long i = (long)blockIdx.x * blockDim.x + threadIdx.x;
    long stride = (long)gridDim.x * blockDim.x;
    for (; i < n4; i += stride) {
        float4 v = ((const float4*)src)[i];
        float4 o;
        o.x = rtf(v.x); o.y = rtf(v.y); o.z = rtf(v.z); o.w = rtf(v.w);
        ((float4*)dst)[i] = o;
    }
}

__global__ void round_pad_wdt_h(const float* __restrict__ src, __half* __restrict__ dst) {
    int i = blockIdx.x * blockDim.x + threadIdx.x;
    if (i >= DIX * 128) return;
    int d = i >> 7, r = i & 127;
    dst[i] = __float2half_rn((r < DTR) ? src[d * DTR + r] : 0.f);
}

// zero a float buffer (float4 grid-stride)
__global__ void zero_f_kernel(float* __restrict__ p, long n4) {
    long i = (long)blockIdx.x * blockDim.x + threadIdx.x;
    long stride = (long)gridDim.x * blockDim.x;
    float4 z = make_float4(0.f, 0.f, 0.f, 0.f);
    for (; i < n4; i += stride) ((float4*)p)[i] = z;
}

// fixed-order sum of KSPLIT fp32 slices -> half
__global__ void reduce4h_kernel(const float* __restrict__ src, long sliceElems,
                                __half* __restrict__ out, long n4) {
    long i = (long)blockIdx.x * blockDim.x + threadIdx.x;
    if (i >= n4) return;
    float4 a = ((const float4*)src)[i];
    #pragma unroll
    for (int s = 1; s < KSPLIT; s++) {
        float4 b = ((const float4*)(src + s * sliceElems))[i];
        a.x += b.x; a.y += b.y; a.z += b.z; a.w += b.w;
    }
    ((__half2*)out)[i * 2 + 0] = __floats2half2_rn(a.x, a.y);
    ((__half2*)out)[i * 2 + 1] = __floats2half2_rn(a.z, a.w);
}

// ---------------- common async helpers ---------------------------------------
__device__ __forceinline__ void cpa16(uint32_t dst, const void* src, bool pred) {
    int sz = pred ? 16 : 0;
    asm volatile("cp.async.cg.shared.global [%0], [%1], 16, %2;\n"
                 :: "r"(dst), "l"(src), "r"(sz));
}
__device__ __forceinline__ void cp_commit() {
    asm volatile("cp.async.commit_group;\n");
}
template <int n>
__device__ __forceinline__ void cp_wait() {
    asm volatile("cp.async.wait_group %0;\n" :: "n"(n));
}

// ============================================================================
// FP16 transB GEMM. OUT: 0 = float store, 1 = half store, 2 = float slice
// (split-K partial, slice z at Cv + z*sCz). Single-barrier mainloop.
// ============================================================================
#define HSTR_B 48
#define HTILE  (128 * HSTR_B)
#define HSTG   (2 * HTILE)
#define HSTAGES 4
#define H_SMEM (HSTAGES * HSTG)

__device__ __forceinline__ void ldsm4(uint32_t& r0, uint32_t& r1, uint32_t& r2,
                                      uint32_t& r3, uint32_t addr) {
    asm volatile("ldmatrix.sync.aligned.m8n8.x4.shared.b16 {%0,%1,%2,%3}, [%4];"
                 : "=r"(r0), "=r"(r1), "=r"(r2), "=r"(r3) : "r"(addr));
}

__device__ __forceinline__ void mma_f16(float* c, const uint32_t* a, const uint32_t* b) {
    asm volatile(
        "mma.sync.aligned.m16n8k16.row.col.f32.f16.f16.f32 "
        "{%0,%1,%2,%3}, {%4,%5,%6,%7}, {%8,%9}, {%0,%1,%2,%3};\n"
        : "+f"(c[0]), "+f"(c[1]), "+f"(c[2]), "+f"(c[3])
        : "r"(a[0]), "r"(a[1]), "r"(a[2]), "r"(a[3]), "r"(b[0]), "r"(b[1]));
}

template <int OUT>
__global__ void __launch_bounds__(256, 2) gemm_f16_pipe(
    const __half* __restrict__ A, const __half* __restrict__ Bp, void* __restrict__ Cv,
    int M, int N, int K, int lda, int ldb, int ldc, int kc, long sCz,
    const float* __restrict__ biasN, const float* __restrict__ resid, int act) {
    extern __shared__ char hsm[];
    uint32_t smbase = (uint32_t)__cvta_generic_to_shared(hsm);

    int m0 = blockIdx.y * 128, n0 = blockIdx.x * 128;
    int zk = blockIdx.z;
    int k0base = zk * kc;
    int kend = min(K, k0base + kc);
    int niter = (kend - k0base) >> 4;

    int tid = threadIdx.x;
    int warp = tid >> 5, lane = tid & 31;
    int wm = (warp >> 1) * 32;
    int wn = (warp & 1) * 64;
    int lr = lane >> 2, lc = lane & 3;

    float acc[2][8][4];
    #pragma unroll
    for (int i = 0; i < 2; i++)
        #pragma unroll
        for (int j = 0; j < 8; j++)
            #pragma unroll
            for (int q = 0; q < 4; q++) acc[i][j][q] = 0.f;

    int q = lane >> 3, rr = lane & 7;
    uint32_t aLane = (uint32_t)((((q == 1 || q == 3) ? 8 : 0) + rr) * HSTR_B +
                                ((q >= 2) ? 16 : 0));
    uint32_t bLane = (uint32_t)((((q >= 2) ? 8 : 0) + rr) * HSTR_B +
                                ((q & 1) ? 16 : 0));

    int lrow = tid >> 1, lseg = tid & 1;

    auto load_stage = [&](int kt, int st) {
        int k0 = k0base + kt * 16;
        uint32_t ab = smbase + (uint32_t)(st * HSTG);
        uint32_t bb = ab + HTILE;
        cpa16(ab + (uint32_t)(lrow * HSTR_B + lseg * 16),
              A + (long)(m0 + lrow) * lda + k0 + lseg * 8, (m0 + lrow) < M);
        cpa16(bb + (uint32_t)(lrow * HSTR_B + lseg * 16),
              Bp + (long)(n0 + lrow) * ldb + k0 + lseg * 8, (n0 + lrow) < N);
    };

    #pragma unroll
    for (int s = 0; s < HSTAGES - 1; s++) { load_stage(s, s); cp_commit(); }

    for (int it = 0; it < niter; it++) {
        cp_wait<HSTAGES - 2>();
        __syncthreads();

        int st = it % HSTAGES;
        uint32_t ab = smbase + (uint32_t)(st * HSTG);
        uint32_t bb = ab + HTILE;

        uint32_t af[2][4];
        #pragma unroll
        for (int im = 0; im < 2; im++)
            ldsm4(af[im][0], af[im][1], af[im][2], af[im][3],
                  ab + (uint32_t)((wm + im * 16) * HSTR_B) + aLane);
        uint32_t bf[4][4];
        #pragma unroll
        for (int j = 0; j < 4; j++)
            ldsm4(bf[j][0], bf[j][1], bf[j][2], bf[j][3],
                  bb + (uint32_t)((wn + j * 16) * HSTR_B) + bLane);

        #pragma unroll
        for (int im = 0; im < 2; im++)
            #pragma unroll
            for (int j = 0; j < 4; j++) {
                uint32_t blo[2] = { bf[j][0], bf[j][1] };
                uint32_t bhi[2] = { bf[j][2], bf[j][3] };
                mma_f16(acc[im][2 * j + 0], af[im], blo);
                mma_f16(acc[im][2 * j + 1], af[im], bhi);
            }

        int kp = it + HSTAGES - 1;
        if (kp < niter) load_stage(kp, kp % HSTAGES);
        cp_commit();
    }

    // ---- epilogue ----
    #pragma unroll
    for (int im = 0; im < 2; im++) {
        #pragma unroll
        for (int rr2 = 0; rr2 < 2; rr2++) {
            int gm = m0 + wm + im * 16 + lr + rr2 * 8;
            if (gm >= M) continue;
            #pragma unroll
            for (int in_ = 0; in_ < 8; in_++) {
                int gn = n0 + wn + in_ * 8 + 2 * lc;
                float v0 = acc[im][in_][rr2 * 2 + 0];
                float v1 = acc[im][in_][rr2 * 2 + 1];
                if (OUT != 2) {
                    if (biasN) {
                        if (gn + 0 < N) v0 += biasN[gn + 0];
                        if (gn + 1 < N) v1 += biasN[gn + 1];
                    }
                    if (resid) {
                        if (gn + 0 < N) v0 += resid[(long)gm * ldc + gn + 0];
                        if (gn + 1 < N) v1 += resid[(long)gm * ldc + gn + 1];
                    }
                    if (act == 2) {
                        v0 = fmaxf(v0, 0.f) + __logf(1.f + __expf(-fabsf(v0)));
                        v1 = fmaxf(v1, 0.f) + __logf(1.f + __expf(-fabsf(v1)));
                    }
                }
                if (OUT == 1) {
                    __half* cp = (__half*)Cv + (long)gm * ldc + gn;
                    if (gn + 1 < N) {
                        *(__half2*)cp = __floats2half2_rn(v0, v1);
                    } else if (gn < N) {
                        cp[0] = __float2half_rn(v0);
                    }
                } else {
                    float* base = (OUT == 2) ? (float*)Cv + (long)zk * sCz : (float*)Cv;
                    float* cp = base + (long)gm * ldc + gn;
                    if (gn + 1 < N && ((((uintptr_t)cp) & 7) == 0)) {
                        *(float2*)cp = make_float2(v0, v1);
                    } else {
                        if (gn + 0 < N) cp[0] = v0;
                        if (gn + 1 < N) cp[1] = v1;
                    }
                }
            }
        }
    }
}

// ============================================================================
// TF32 notrans GEMM (conv1/conv3), single-barrier mainloop
// ============================================================================
#define ASTRN 20
#define BSTRN 136
#define TSTAGES 4
#define TASZ   3072
#define TBSZ   3072
#define TSTG_W (TASZ + TBSZ)
#define T_SMEM (TSTAGES * TSTG_W * 4)

__device__ __forceinline__ void mma_tf32(float* c, const uint32_t* a, const uint32_t* b) {
    asm volatile(
        "mma.sync.aligned.m16n8k8.row.col.f32.tf32.tf32.f32 "
        "{%0,%1,%2,%3}, {%4,%5,%6,%7}, {%8,%9}, {%0,%1,%2,%3};\n"
        : "+f"(c[0]), "+f"(c[1]), "+f"(c[2]), "+f"(c[3])
        : "r"(a[0]), "r"(a[1]), "r"(a[2]), "r"(a[3]), "r"(b[0]), "r"(b[1]));
}

__global__ void __launch_bounds__(256, 2) gemm_tf32_conv(
    const float* __restrict__ A, const float* __restrict__ Bp, float* __restrict__ C,
    int M, int N, int K, int lda, int ldb, int ldc,
    long sB, long sC,
    const float* __restrict__ biasM, const float* __restrict__ resid, long sR) {
    extern __shared__ float sm[];
    uint32_t smbase = (uint32_t)__cvta_generic_to_shared(sm);

    int z = blockIdx.z;
    Bp += (long)z * sB;
    C  += (long)z * sC;

    int m0 = blockIdx.y * 128, n0 = blockIdx.x * 128;
    int tid = threadIdx.x;
    int warp = tid >> 5, lane = tid & 31;
    int wm = (warp >> 1) * 32;
    int wn = (warp & 1) * 64;
    int lr = lane >> 2, lc = lane & 3;

    float acc[2][8][4];
    #pragma unroll
    for (int i = 0; i < 2; i++)
        #pragma unroll
        for (int j = 0; j < 8; j++)
            #pragma unroll
            for (int q = 0; q < 4; q++) acc[i][j][q] = 0.f;

    int a_row[2], a_c4[2];
    #pragma unroll
    for (int j = 0; j < 2; j++) {
        int f = tid + j * 256;
        a_row[j] = f >> 2;
        a_c4[j]  = (f & 3) * 4;
    }

    auto load_stage = [&](int k0, int st) {
        uint32_t abase = smbase + (uint32_t)(st * TSTG_W * 4);
        uint32_t bbase = abase + (uint32_t)(TASZ * 4);
        #pragma unroll
        for (int j = 0; j < 2; j++) {
            int row = a_row[j], c4 = a_c4[j];
            int gm = m0 + row;
            cpa16(abase + (uint32_t)((row * ASTRN + c4) * 4),
                  A + (long)gm * lda + k0 + c4, gm < M);
        }
        #pragma unroll
        for (int j = 0; j < 2; j++) {
            int f = tid + j * 256;
            int kk = f >> 5, n4 = (f & 31) * 4;
            int gn = n0 + n4;
            cpa16(bbase + (uint32_t)((kk * BSTRN + n4) * 4),
                  Bp + (long)(k0 + kk) * ldb + gn, gn < N);
        }
    };

    int niter = K >> 4;

    #pragma unroll
    for (int s = 0; s < TSTAGES - 1; s++) { load_stage(s * 16, s); cp_commit(); }

    for (int it = 0; it < niter; it++) {
        cp_wait<TSTAGES - 2>();
        __syncthreads();

        int st = it % TSTAGES;
        const float* Asm = sm + st * TSTG_W;
        const float* Bsm = Asm + TASZ;
        const uint32_t* Au = (const uint32_t*)Asm;
        const uint32_t* Bu = (const uint32_t*)Bsm;

        #pragma unroll
        for (int kk = 0; kk < 2; kk++) {
            int kb = kk * 8;
            uint32_t af[2][4];
            uint32_t bfr[8][2];
            #pragma unroll
            for (int im = 0; im < 2; im++) {
                int r = wm + im * 16 + lr;
                af[im][0] = Au[r * ASTRN + kb + lc];
                af[im][1] = Au[(r + 8) * ASTRN + kb + lc];
                af[im][2] = Au[r * ASTRN + kb + lc + 4];
                af[im][3] = Au[(r + 8) * ASTRN + kb + lc + 4];
            }
            #pragma unroll
            for (int in_ = 0; in_ < 8; in_++) {
                int nn = wn + in_ * 8 + lr;
                bfr[in_][0] = Bu[(kb + lc) * BSTRN + nn];
                bfr[in_][1] = Bu[(kb + lc + 4) * BSTRN + nn];
            }
            #pragma unroll
            for (int im = 0; im < 2; im++)
                #pragma unroll
                for (int in_ = 0; in_ < 8; in_++)
                    mma_tf32(acc[im][in_], af[im], bfr[in_]);
        }

        int kp = it + TSTAGES - 1;
        if (kp < niter) load_stage(kp * 16, kp % TSTAGES);
        cp_commit();
    }

    if (resid) resid += (long)z * sR;
    #pragma unroll
    for (int im = 0; im < 2; im++) {
        #pragma unroll
        for (int rr = 0; rr < 2; rr++) {
            int gm = m0 + wm + im * 16 + lr + rr * 8;
            if (gm >= M) continue;
            float bm = biasM ? biasM[gm] : 0.f;
            #pragma unroll
            for (int in_ = 0; in_ < 8; in_++) {
                int gn = n0 + wn + in_ * 8 + 2 * lc;
                float v0 = acc[im][in_][rr * 2 + 0] + bm;
                float v1 = acc[im][in_][rr * 2 + 1] + bm;
                if (resid) {
                    if (gn + 0 < N) v0 += resid[(long)gm * ldc + gn + 0];
                    if (gn + 1 < N) v1 += resid[(long)gm * ldc + gn + 1];
                }
                float* cp = &C[(long)gm * ldc + gn];
                if (gn + 1 < N && ((((uintptr_t)cp) & 7) == 0)) {
                    *(float2*)cp = make_float2(v0, v1);
                } else {
                    if (gn + 0 < N) cp[0] = v0;
                    if (gn + 1 < N) cp[1] = v1;
                }
            }
        }
    }
}

// ---------------- host side --------------------------------------------------
static void launch_gemm_f16(const __half* A, const __half* B, void* C,
                            int M, int N, int K, int lda, int ldb, int ldc,
                            int outmode, const float* biasN, const float* resid,
                            int act) {
    dim3 grid((N + 127) / 128, (M + 127) / 128, 1);
    if (outmode == 1) {
        cudaFuncSetAttribute(gemm_f16_pipe<1>,
                             cudaFuncAttributeMaxDynamicSharedMemorySize, H_SMEM);
        gemm_f16_pipe<1><<<grid, 256, H_SMEM>>>(A, B, C, M, N, K, lda, ldb, ldc,
                                                K, 0, biasN, resid, act);
    } else {
        cudaFuncSetAttribute(gemm_f16_pipe<0>,
                             cudaFuncAttributeMaxDynamicSharedMemorySize, H_SMEM);
        gemm_f16_pipe<0><<<grid, 256, H_SMEM>>>(A, B, C, M, N, K, lda, ldb, ldc,
                                                K, 0, biasN, resid, act);
    }
}

extern "C" void kernel_launch(void* const* d_in, const int* in_sizes, int n_in,
                              void* d_out, int out_size) {
    const float* x       = (const float*)d_in[0];
    const float* bn1_g   = (const float*)d_in[1];
    const float* bn1_b   = (const float*)d_in[2];
    const float* conv1_w = (const float*)d_in[3];
    const float* conv1_b = (const float*)d_in[4];
    const float* ln_w    = (const float*)d_in[5];
    const float* ln_b    = (const float*)d_in[6];
    const float* W_in    = (const float*)d_in[7];
    const float* convm_w = (const float*)d_in[8];
    const float* convm_b = (const float*)d_in[9];
    const float* W_x     = (const float*)d_in[10];
    const float* W_dt    = (const float*)d_in[11];
    const float* b_dt    = (const float*)d_in[12];
    const float* A_log   = (const float*)d_in[13];
    const float* D_p     = (const float*)d_in[14];
    const float* W_out   = (const float*)d_in[15];
    const float* bn3_g   = (const float*)d_in[16];
    const float* bn3_b   = (const float*)d_in[17];
    const float* conv3_w = (const float*)d_in[18];
    const float* conv3_b = (const float*)d_in[19];
    float* out = (float*)d_out;

    float *pm1, *pr1, *pcm1, *pcr1, *pmL, *prL, *pm3, *pr3, *pcm3, *pcr3;
    float *ph, *ph1, *pres, *pc1w, *pc3w, *pxdbl4;
    __half *poutnh, *pxzh, *pxch, *pxdblh, *pdth, *pyh;
    __half *pwinh, *pwouth, *pwxh, *pwdth;
    cudaGetSymbolAddress((void**)&pm1,  g_m1);
    cudaGetSymbolAddress((void**)&pr1,  g_r1);
    cudaGetSymbolAddress((void**)&pcm1, g_cm1);
    cudaGetSymbolAddress((void**)&pcr1, g_cr1);
    cudaGetSymbolAddress((void**)&pmL,  g_mL);
    cudaGetSymbolAddress((void**)&prL,  g_rL);
    cudaGetSymbolAddress((void**)&pm3,  g_m3);
    cudaGetSymbolAddress((void**)&pr3,  g_r3);
    cudaGetSymbolAddress((void**)&pcm3, g_cm3);
    cudaGetSymbolAddress((void**)&pcr3, g_cr3);
    cudaGetSymbolAddress((void**)&ph,    g_h);
    cudaGetSymbolAddress((void**)&ph1,   g_h1);
    cudaGetSymbolAddress((void**)&pres,  g_res);
    cudaGetSymbolAddress((void**)&pxdbl4, g_xdbl4);
    cudaGetSymbolAddress((void**)&poutnh, g_outnh);
    cudaGetSymbolAddress((void**)&pxzh,   g_xzh);
    cudaGetSymbolAddress((void**)&pxch,   g_xch);
    cudaGetSymbolAddress((void**)&pxdblh, g_xdblh);
    cudaGetSymbolAddress((void**)&pdth,   g_dth);
    cudaGetSymbolAddress((void**)&pyh,    g_yh);
    cudaGetSymbolAddress((void**)&pwinh,  g_winh);
    cudaGetSymbolAddress((void**)&pwouth, g_wouth);
    cudaGetSymbolAddress((void**)&pwxh,   g_wxh);
    cudaGetSymbolAddress((void**)&pwdth,  g_wdth);
    cudaGetSymbolAddress((void**)&pc1w,  g_c1w);
    cudaGetSymbolAddress((void**)&pc3w,  g_c3w);

    const int EW_BLK = 256;
    const size_t nBCN4 = (size_t)ROWS * (NDIM / 4);
    int gBCN4 = (int)((nBCN4 + EW_BLK - 1) / EW_BLK);
    const size_t nBLD4 = (size_t)ROWS * (DIX / 4);
    int gBLD4 = (int)((nBLD4 + EW_BLK - 1) / EW_BLK);

    // ---- weight conversion + split-K slice zero ----
    round_half_kernel<<<1024, 256>>>(W_in,  pwinh,  (long)DIN2 * NDIM / 4);
    round_half_kernel<<<1024, 256>>>(W_out, pwouth, (long)NDIM * DIX / 4);
    round_half_kernel<<<256,  256>>>(W_x,   pwxh,   (long)XCOLS * DIX / 4);
    round_tf32_kernel<<<16,   256>>>(conv1_w, pc1w, (long)CCH * CCH / 4);
    round_tf32_kernel<<<16,   256>>>(conv3_w, pc3w, (long)CCH * CCH / 4);
    round_pad_wdt_h<<<(DIX * 128 + 255) / 256, 256>>>(W_dt, pwdth);
    zero_f_kernel<<<512, 256>>>(pxdbl4, (long)KSPLIT * ROWS * XSTR / 4);

    // ---- Block 1: inorm -> bnorm(analytic) -> relu -> 1x1 conv (tf32) ----
    rowstat_kernel<<<ROWS, 256>>>(x, pm1, pr1, 1e-3f);
    chanstat_fast<<<1, CCH>>>(pr1, pcm1, pcr1, 1e-3f, 1e-5f);
    normrelu_kernel<<<gBCN4, EW_BLK>>>(x, pm1, pr1, pcm1, pcr1, bn1_g, bn1_b, ph);
    {
        dim3 grid((NDIM + 127) / 128, 1, BATCH);
        cudaFuncSetAttribute(gemm_tf32_conv,
                             cudaFuncAttributeMaxDynamicSharedMemorySize, T_SMEM);
        gemm_tf32_conv<<<grid, 256, T_SMEM>>>(pc1w, ph, ph1, CCH, NDIM, CCH,
                                              CCH, NDIM, NDIM,
                                              (long)CCH * NDIM, (long)CCH * NDIM,
                                              conv1_b, nullptr, 0);
    }

    // ---- LayerNorm over N -> half ----
    rowstat_kernel<<<ROWS, 256>>>(ph1, pmL, prL, 1e-5f);
    lnapply_h_kernel<<<gBCN4, EW_BLK>>>(ph1, pmL, prL, ln_w, ln_b, poutnh);

    // ---- Mamba (fp16 GEMMs) ----
    launch_gemm_f16(poutnh, pwinh, pxzh, ROWS, DIN2, NDIM, NDIM, NDIM, DIN2,
                    1, nullptr, nullptr, 0);
    convm_silu_h_kernel<<<gBLD4, EW_BLK>>>(pxzh, convm_w, convm_b, pxch);
    // W_x GEMM: split-K over 4 slices (deterministic), then reduce -> half
    {
        dim3 grid((XCOLS + 127) / 128, ROWS / 128, KSPLIT);
        cudaFuncSetAttribute(gemm_f16_pipe<2>,
                             cudaFuncAttributeMaxDynamicSharedMemorySize, H_SMEM);
        gemm_f16_pipe<2><<<grid, 256, H_SMEM>>>(pxch, pwxh, pxdbl4,
                                                ROWS, XCOLS, DIX, DIX, DIX, XSTR,
                                                KCHUNK, (long)ROWS * XSTR,
                                                nullptr, nullptr, 0);
        reduce4h_kernel<<<(ROWS * XSTR / 4 + 255) / 256, 256>>>(
            pxdbl4, (long)ROWS * XSTR, pxdblh, (long)ROWS * XSTR / 4);
    }
    launch_gemm_f16(pxdblh, pwdth, pdth, ROWS, DIX, 128, XSTR, 128, DIX,
                    1, b_dt, nullptr, 2);
    scan_h_kernel<<<(BATCH * DIX + 255) / 256, 256>>>(pdth, pxch, pxdblh, pxzh,
                                                      A_log, D_p, pyh);
    launch_gemm_f16(pyh, pwouth, pres, ROWS, NDIM, DIX, DIX, DIX, NDIM,
                    0, nullptr, ph1, 0);

    // ---- Block 3 (tf32 conv + input residual) ----
    rowstat_kernel<<<ROWS, 256>>>(pres, pm3, pr3, 1e-3f);
    chanstat_fast<<<1, CCH>>>(pr3, pcm3, pcr3, 1e-3f, 1e-5f);
    normrelu_kernel<<<gBCN4, EW_BLK>>>(pres, pm3, pr3, pcm3, pcr3, bn3_g, bn3_b, ph);
    {
        dim3 grid((NDIM + 127) / 128, 1, BATCH);
        cudaFuncSetAttribute(gemm_tf32_conv,
                             cudaFuncAttributeMaxDynamicSharedMemorySize, T_SMEM);
        gemm_tf32_conv<<<grid, 256, T_SMEM>>>(pc3w, ph, out, CCH, NDIM, CCH,
                                              CCH, NDIM, NDIM,
                                              (long)CCH * NDIM, (long)CCH * NDIM,
                                              conv3_b, x, (long)CCH * NDIM);
    }
}